// round 1
// baseline (speedup 1.0000x reference)
#include <cuda_runtime.h>
#include <cuda_bf16.h>

// Counterfactual neural-ODE: fixed-step RK4, one step per ts-segment (steps
// aligned to the treatment-interpolation kinks, so each segment's RHS is
// smooth). Single CTA of 64 threads; MLP weights live in registers
// (thread t owns W1[:,t], W2[:,t], and half of W3[:,t&31]); activations are
// broadcast through tiny SMEM buffers with float4 loads.

__device__ __forceinline__ float ftanh(float x) {
    // tanh(x) = 1 - 2/(exp(2x)+1); MUFU.EX2 + MUFU.RCP, ~1e-6 accuracy.
    float e = __expf(2.0f * x);
    return 1.0f - __fdividef(2.0f, e + 1.0f);
}

__global__ void __launch_bounds__(64, 1)
ode_rk4_kernel(const float* __restrict__ x0,
               const float* __restrict__ treat,   // [100,4]
               const float* __restrict__ ts,      // [100]
               const float* __restrict__ W1,      // [36,64]
               const float* __restrict__ b1,      // [64]
               const float* __restrict__ W2,      // [64,64]
               const float* __restrict__ b2,      // [64]
               const float* __restrict__ W3,      // [64,32]
               const float* __restrict__ b3,      // [32]
               float* __restrict__ out)           // [100,32]
{
    __shared__ __align__(16) float sbuf[36];   // augmented state (x:32, tr:4)
    __shared__ __align__(16) float h1b[64];
    __shared__ __align__(16) float h2b[64];
    __shared__ __align__(16) float p3b[32];    // cross-warp layer-3 partials
    __shared__ float trb[400];
    __shared__ float tsb[104];

    const int t    = threadIdx.x;
    const int i3   = t & 31;         // layer-3 output this thread contributes to
    const int kq   = (t >> 5) * 8;   // float4 offset into h2b for this thread's k-range

    // ---- weights into registers (fully unrolled -> register arrays) ----
    float w1[36], w2[64], w3[32];
#pragma unroll
    for (int i = 0; i < 36; ++i) w1[i] = W1[i * 64 + t];
#pragma unroll
    for (int k = 0; k < 64; ++k) w2[k] = W2[k * 64 + t];
#pragma unroll
    for (int k = 0; k < 32; ++k) w3[k] = W3[((t >> 5) * 32 + k) * 32 + i3];
    const float bb1 = b1[t];
    const float bb2 = b2[t];
    const float bb3 = (t < 32) ? b3[t] : 0.0f;

    for (int j = t; j < 400; j += 64) trb[j] = treat[j];
    for (int j = t; j < 100; j += 64) tsb[j] = ts[j];

    float x = 0.0f;
    if (t < 32) { x = x0[t]; out[t] = x; }
    __syncthreads();

    float trA = 0.0f, trB = 0.0f;

    // One RHS evaluation. Caller passes this thread's stage-state component
    // (valid for t<32) and the treatment interpolation weight w in [0,1].
    auto eval = [&](float xs, float w) -> float {
        if (t < 32) sbuf[t] = xs;
        if (t < 4)  sbuf[32 + t] = trA + w * (trB - trA);
        __syncthreads();                                  // bar A: sbuf ready

        // layer 1: h1[t] = tanh(s . W1[:,t] + b1[t])
        float a0 = bb1, a1 = 0.f, a2 = 0.f, a3 = 0.f;
        const float4* s4 = (const float4*)sbuf;
#pragma unroll
        for (int q = 0; q < 9; ++q) {
            float4 v = s4[q];
            a0 = fmaf(v.x, w1[4 * q + 0], a0);
            a1 = fmaf(v.y, w1[4 * q + 1], a1);
            a2 = fmaf(v.z, w1[4 * q + 2], a2);
            a3 = fmaf(v.w, w1[4 * q + 3], a3);
        }
        h1b[t] = ftanh((a0 + a1) + (a2 + a3));
        __syncthreads();                                  // bar B: h1 ready

        // layer 2: h2[t] = tanh(h1 . W2[:,t] + b2[t])
        float c0 = bb2, c1 = 0.f, c2 = 0.f, c3 = 0.f;
        const float4* h4 = (const float4*)h1b;
#pragma unroll
        for (int q = 0; q < 16; ++q) {
            float4 v = h4[q];
            c0 = fmaf(v.x, w2[4 * q + 0], c0);
            c1 = fmaf(v.y, w2[4 * q + 1], c1);
            c2 = fmaf(v.z, w2[4 * q + 2], c2);
            c3 = fmaf(v.w, w2[4 * q + 3], c3);
        }
        h2b[t] = ftanh((c0 + c1) + (c2 + c3));
        __syncthreads();                                  // bar C: h2 ready

        // layer 3: dx[i3] = h2 . W3[:,i3] + b3[i3], split k-range across warps
        float d0 = 0.f, d1 = 0.f, d2 = 0.f, d3 = 0.f;
        const float4* g4 = (const float4*)h2b;
#pragma unroll
        for (int q = 0; q < 8; ++q) {
            float4 v = g4[kq + q];
            d0 = fmaf(v.x, w3[4 * q + 0], d0);
            d1 = fmaf(v.y, w3[4 * q + 1], d1);
            d2 = fmaf(v.z, w3[4 * q + 2], d2);
            d3 = fmaf(v.w, w3[4 * q + 3], d3);
        }
        float p = (d0 + d1) + (d2 + d3);
        if (t >= 32) p3b[i3] = p;
        __syncthreads();                                  // bar D: partials ready

        float kv = 0.0f;
        if (t < 32) kv = p + p3b[i3] + bb3;
        return kv;
    };

    for (int seg = 0; seg < 99; ++seg) {
        const float hseg = tsb[seg + 1] - tsb[seg];
        if (t < 4) {
            trA = trb[seg * 4 + t];
            trB = trb[seg * 4 + 4 + t];
        }

        const float k1 = eval(x, 0.0f);
        const float k2 = eval(x + 0.5f * hseg * k1, 0.5f);
        const float k3 = eval(x + 0.5f * hseg * k2, 0.5f);
        const float k4 = eval(x + hseg * k3, 1.0f);

        if (t < 32) {
            x += hseg * (1.0f / 6.0f) * (k1 + 2.0f * (k2 + k3) + k4);
            out[(seg + 1) * 32 + t] = x;
        }
    }
}

extern "C" void kernel_launch(void* const* d_in, const int* in_sizes, int n_in,
                              void* d_out, int out_size) {
    const float* x0    = (const float*)d_in[0];
    const float* treat = (const float*)d_in[1];
    const float* ts    = (const float*)d_in[2];
    const float* W1    = (const float*)d_in[3];
    const float* b1    = (const float*)d_in[4];
    const float* W2    = (const float*)d_in[5];
    const float* b2    = (const float*)d_in[6];
    const float* W3    = (const float*)d_in[7];
    const float* b3    = (const float*)d_in[8];
    float* out = (float*)d_out;

    ode_rk4_kernel<<<1, 64>>>(x0, treat, ts, W1, b1, W2, b2, W3, b3, out);
}

// round 2
// speedup vs baseline: 1.7968x; 1.7968x over previous
#include <cuda_runtime.h>
#include <cuda_bf16.h>

// Counterfactual neural-ODE. Midpoint RK2, one step per ts-segment (steps
// aligned to the treatment-interpolation kinks => RHS smooth inside a step;
// truncation ~1e-5 vs 1e-3 budget). Single CTA, 64 threads, weights in
// registers, packed f32x2 FMA for 2 MACs/instruction, activations broadcast
// through SMEM as pre-packed 16B vectors.

__device__ __forceinline__ unsigned long long pack2(float lo, float hi) {
    unsigned long long r;
    asm("mov.b64 %0, {%1, %2};" : "=l"(r) : "f"(lo), "f"(hi));
    return r;
}
__device__ __forceinline__ void unpack2(unsigned long long v, float& lo, float& hi) {
    asm("mov.b64 {%0, %1}, %2;" : "=f"(lo), "=f"(hi) : "l"(v));
}
__device__ __forceinline__ void ffma2(unsigned long long& d,
                                      unsigned long long a, unsigned long long b) {
    asm("fma.rn.f32x2 %0, %1, %2, %3;" : "=l"(d) : "l"(a), "l"(b), "l"(d));
}
__device__ __forceinline__ unsigned long long addf2(unsigned long long a,
                                                    unsigned long long b) {
    unsigned long long d;
    asm("add.rn.f32x2 %0, %1, %2;" : "=l"(d) : "l"(a), "l"(b));
    return d;
}

__device__ __forceinline__ float ftanh(float x) {
    // tanh(x) = 1 - 2/(exp(2x)+1); MUFU.EX2 + MUFU.RCP, ~1e-6 accuracy.
    float e = __expf(2.0f * x);
    return 1.0f - __fdividef(2.0f, e + 1.0f);
}

__global__ void __launch_bounds__(64, 1)
ode_rk2_kernel(const float* __restrict__ x0,
               const float* __restrict__ treat,   // [100,4]
               const float* __restrict__ ts,      // [100]
               const float* __restrict__ W1,      // [36,64]
               const float* __restrict__ b1,      // [64]
               const float* __restrict__ W2,      // [64,64]
               const float* __restrict__ b2,      // [64]
               const float* __restrict__ W3,      // [64,32]
               const float* __restrict__ b3,      // [32]
               float* __restrict__ out)           // [100,32]
{
    __shared__ __align__(16) float sbuf[36];   // augmented state (x:32, tr:4)
    __shared__ __align__(16) float h1b[64];
    __shared__ __align__(16) float h2b[64];
    __shared__ __align__(16) float p3b[32];    // cross-warp layer-3 partials
    __shared__ float trb[400];
    __shared__ float tsb[104];

    const int t    = threadIdx.x;
    const int i3   = t & 31;         // layer-3 output this thread contributes to
    const int kq   = (t >> 5) * 8;   // float4 offset into h2b for this thread's k-range
    const int kb   = (t >> 5) * 32;  // base K index for layer-3 split

    // ---- weights into registers, packed as f32x2 pairs ----
    unsigned long long w1p[18], w2p[32], w3p[16];
#pragma unroll
    for (int j = 0; j < 18; ++j)
        w1p[j] = pack2(W1[(2 * j) * 64 + t], W1[(2 * j + 1) * 64 + t]);
#pragma unroll
    for (int j = 0; j < 32; ++j)
        w2p[j] = pack2(W2[(2 * j) * 64 + t], W2[(2 * j + 1) * 64 + t]);
#pragma unroll
    for (int j = 0; j < 16; ++j)
        w3p[j] = pack2(W3[(kb + 2 * j) * 32 + i3], W3[(kb + 2 * j + 1) * 32 + i3]);
    const float bb1 = b1[t];
    const float bb2 = b2[t];
    const float bb3 = (t < 32) ? b3[t] : 0.0f;

    for (int j = t; j < 400; j += 64) trb[j] = treat[j];
    for (int j = t; j < 100; j += 64) tsb[j] = ts[j];

    float x = 0.0f;
    if (t < 32) { x = x0[t]; out[t] = x; }
    __syncthreads();

    float trA = 0.0f, trB = 0.0f;

    // One RHS evaluation; xs = this thread's stage-state component (t<32),
    // w = treatment interpolation weight.
    auto eval = [&](float xs, float w) -> float {
        if (t < 32) sbuf[t] = xs;
        if (t < 4)  sbuf[32 + t] = trA + w * (trB - trA);
        __syncthreads();                                  // bar A: sbuf ready

        // layer 1: h1[t] = tanh(s . W1[:,t] + b1[t])
        unsigned long long a01 = pack2(bb1, 0.0f), a23 = 0ull;
        const ulonglong2* s2 = (const ulonglong2*)sbuf;
#pragma unroll
        for (int q = 0; q < 9; ++q) {
            ulonglong2 v = s2[q];
            ffma2(a01, v.x, w1p[2 * q]);
            ffma2(a23, v.y, w1p[2 * q + 1]);
        }
        {
            float lo, hi;
            unpack2(addf2(a01, a23), lo, hi);
            h1b[t] = ftanh(lo + hi);
        }
        __syncthreads();                                  // bar B: h1 ready

        // layer 2: h2[t] = tanh(h1 . W2[:,t] + b2[t])
        unsigned long long c01 = pack2(bb2, 0.0f), c23 = 0ull;
        const ulonglong2* h2v = (const ulonglong2*)h1b;
#pragma unroll
        for (int q = 0; q < 16; ++q) {
            ulonglong2 v = h2v[q];
            ffma2(c01, v.x, w2p[2 * q]);
            ffma2(c23, v.y, w2p[2 * q + 1]);
        }
        {
            float lo, hi;
            unpack2(addf2(c01, c23), lo, hi);
            h2b[t] = ftanh(lo + hi);
        }
        __syncthreads();                                  // bar C: h2 ready

        // layer 3: dx[i3] = h2 . W3[:,i3] + b3[i3], K-range split across warps
        unsigned long long d01 = 0ull, d23 = 0ull;
        const ulonglong2* g2 = (const ulonglong2*)h2b;
#pragma unroll
        for (int q = 0; q < 8; ++q) {
            ulonglong2 v = g2[kq + q];
            ffma2(d01, v.x, w3p[2 * q]);
            ffma2(d23, v.y, w3p[2 * q + 1]);
        }
        float lo, hi;
        unpack2(addf2(d01, d23), lo, hi);
        float p = lo + hi;
        if (t >= 32) p3b[i3] = p;
        __syncthreads();                                  // bar D: partials ready

        float kv = 0.0f;
        if (t < 32) kv = p + p3b[i3] + bb3;
        return kv;
    };

    for (int seg = 0; seg < 99; ++seg) {
        const float hseg = tsb[seg + 1] - tsb[seg];
        if (t < 4) {
            trA = trb[seg * 4 + t];
            trB = trb[seg * 4 + 4 + t];
        }

        // midpoint RK2
        const float k1 = eval(x, 0.0f);
        const float k2 = eval(fmaf(0.5f * hseg, k1, x), 0.5f);

        if (t < 32) {
            x = fmaf(hseg, k2, x);
            out[(seg + 1) * 32 + t] = x;
        }
    }
}

extern "C" void kernel_launch(void* const* d_in, const int* in_sizes, int n_in,
                              void* d_out, int out_size) {
    const float* x0    = (const float*)d_in[0];
    const float* treat = (const float*)d_in[1];
    const float* ts    = (const float*)d_in[2];
    const float* W1    = (const float*)d_in[3];
    const float* b1    = (const float*)d_in[4];
    const float* W2    = (const float*)d_in[5];
    const float* b2    = (const float*)d_in[6];
    const float* W3    = (const float*)d_in[7];
    const float* b3    = (const float*)d_in[8];
    float* out = (float*)d_out;

    ode_rk2_kernel<<<1, 64>>>(x0, treat, ts, W1, b1, W2, b2, W3, b3, out);
}

// round 3
// speedup vs baseline: 1.9598x; 1.0907x over previous
#include <cuda_runtime.h>
#include <cuda_bf16.h>

// Counterfactual neural-ODE. Midpoint RK2, one step per ts-segment.
// Single CTA, 64 threads, weights in registers, packed f32x2 FMA.
// 3 barriers per eval: layer-3 + state update + next-stage publish are fused
// into threads 0-31 (which own the ODE state); treatment contribution to
// layer 1 is hoisted to a per-segment linear term.

__device__ __forceinline__ unsigned long long pack2(float lo, float hi) {
    unsigned long long r;
    asm("mov.b64 %0, {%1, %2};" : "=l"(r) : "f"(lo), "f"(hi));
    return r;
}
__device__ __forceinline__ float hadd2(unsigned long long a, unsigned long long b) {
    unsigned long long s;
    asm("add.rn.f32x2 %0, %1, %2;" : "=l"(s) : "l"(a), "l"(b));
    float lo, hi;
    asm("mov.b64 {%0, %1}, %2;" : "=f"(lo), "=f"(hi) : "l"(s));
    return lo + hi;
}
__device__ __forceinline__ void ffma2(unsigned long long& d,
                                      unsigned long long a, unsigned long long b) {
    asm("fma.rn.f32x2 %0, %1, %2, %3;" : "=l"(d) : "l"(a), "l"(b), "l"(d));
}

__device__ __forceinline__ float ftanh(float x) {
    // tanh(x) = 1 - 2/(exp(2x)+1); MUFU.EX2 + MUFU.RCP, ~1e-6 accuracy.
    float e = __expf(2.0f * x);
    return 1.0f - __fdividef(2.0f, e + 1.0f);
}

__global__ void __launch_bounds__(64, 1)
ode_rk2_kernel(const float* __restrict__ x0,
               const float* __restrict__ treat,   // [100,4]
               const float* __restrict__ ts,      // [100]
               const float* __restrict__ W1,      // [36,64]
               const float* __restrict__ b1,      // [64]
               const float* __restrict__ W2,      // [64,64]
               const float* __restrict__ b2,      // [64]
               const float* __restrict__ W3,      // [64,32]
               const float* __restrict__ b3,      // [32]
               float* __restrict__ out)           // [100,32]
{
    __shared__ __align__(16) float sbuf[32];   // current stage state
    __shared__ __align__(16) float h1b[64];
    __shared__ __align__(16) float h2b[64];
    __shared__ float trb[400];
    __shared__ float tsb[104];

    const int t = threadIdx.x;

    // ---- weights into registers, packed as f32x2 pairs ----
    unsigned long long w1p[16], w2p[32], w3p[32];
#pragma unroll
    for (int j = 0; j < 16; ++j)
        w1p[j] = pack2(W1[(2 * j) * 64 + t], W1[(2 * j + 1) * 64 + t]);
    const float w1t0 = W1[32 * 64 + t];
    const float w1t1 = W1[33 * 64 + t];
    const float w1t2 = W1[34 * 64 + t];
    const float w1t3 = W1[35 * 64 + t];
#pragma unroll
    for (int j = 0; j < 32; ++j)
        w2p[j] = pack2(W2[(2 * j) * 64 + t], W2[(2 * j + 1) * 64 + t]);
    if (t < 32) {
#pragma unroll
        for (int j = 0; j < 32; ++j)
            w3p[j] = pack2(W3[(2 * j) * 32 + t], W3[(2 * j + 1) * 32 + t]);
    }
    const float bb1 = b1[t];
    const float bb2 = b2[t];
    const float bb3 = (t < 32) ? b3[t] : 0.0f;

    for (int j = t; j < 400; j += 64) trb[j] = treat[j];
    for (int j = t; j < 100; j += 64) tsb[j] = ts[j];

    float x = 0.0f;
    if (t < 32) { x = x0[t]; out[t] = x; sbuf[t] = x; }

    // One RHS evaluation. Entering precondition: sbuf holds the stage state
    // (written by t<32), not yet published -> bar A publishes it.
    // be = effective layer-1 bias (b1 + treatment term), ch = step coefficient.
    auto eval = [&](float be, float ch, bool upd, int seg) {
        __syncthreads();                                  // bar A: sbuf ready

        // layer 1: h1[t] = tanh(x . W1[0:32,t] + be)
        unsigned long long a01 = pack2(be, 0.0f), a23 = 0ull;
        const ulonglong2* s2 = (const ulonglong2*)sbuf;
#pragma unroll
        for (int q = 0; q < 8; ++q) {
            ulonglong2 v = s2[q];
            ffma2(a01, v.x, w1p[2 * q]);
            ffma2(a23, v.y, w1p[2 * q + 1]);
        }
        h1b[t] = ftanh(hadd2(a01, a23));
        __syncthreads();                                  // bar B: h1 ready

        // layer 2: h2[t] = tanh(h1 . W2[:,t] + b2[t])
        unsigned long long c01 = pack2(bb2, 0.0f), c23 = 0ull;
        const ulonglong2* h4 = (const ulonglong2*)h1b;
#pragma unroll
        for (int q = 0; q < 16; ++q) {
            ulonglong2 v = h4[q];
            ffma2(c01, v.x, w2p[2 * q]);
            ffma2(c23, v.y, w2p[2 * q + 1]);
        }
        h2b[t] = ftanh(hadd2(c01, c23));
        __syncthreads();                                  // bar C: h2 ready

        // layer 3 + state update: threads 0-31 compute full 64-K dot for
        // output column t, then write the next stage state into sbuf.
        if (t < 32) {
            unsigned long long d01 = 0ull, d23 = 0ull;
            const ulonglong2* g4 = (const ulonglong2*)h2b;
#pragma unroll
            for (int q = 0; q < 16; ++q) {
                ulonglong2 v = g4[q];
                ffma2(d01, v.x, w3p[2 * q]);
                ffma2(d23, v.y, w3p[2 * q + 1]);
            }
            const float kv = hadd2(d01, d23) + bb3;
            if (!upd) {
                sbuf[t] = fmaf(ch, kv, x);                // midpoint stage state
            } else {
                x = fmaf(ch, kv, x);
                out[(seg + 1) * 32 + t] = x;
                sbuf[t] = x;                              // next segment's k1 state
            }
        }
    };

    for (int seg = 0; seg < 99; ++seg) {
        const float hseg = tsb[seg + 1] - tsb[seg];
        // treatment contribution to layer-1 preact: c0 + w*c1 (linear in w)
        const float ta0 = trb[4 * seg + 0], ta1 = trb[4 * seg + 1];
        const float ta2 = trb[4 * seg + 2], ta3 = trb[4 * seg + 3];
        const float c0 = fmaf(w1t0, ta0, fmaf(w1t1, ta1, fmaf(w1t2, ta2, w1t3 * ta3)));
        const float c1 = fmaf(w1t0, trb[4 * seg + 4] - ta0,
                         fmaf(w1t1, trb[4 * seg + 5] - ta1,
                         fmaf(w1t2, trb[4 * seg + 6] - ta2,
                               w1t3 * (trb[4 * seg + 7] - ta3))));
        const float be1 = bb1 + c0;                       // w = 0
        const float be2 = fmaf(0.5f, c1, be1);            // w = 0.5

        eval(be1, 0.5f * hseg, false, seg);               // k1 -> midpoint state
        eval(be2, hseg, true, seg);                       // k2 -> x_{n+1}
    }
}

extern "C" void kernel_launch(void* const* d_in, const int* in_sizes, int n_in,
                              void* d_out, int out_size) {
    const float* x0    = (const float*)d_in[0];
    const float* treat = (const float*)d_in[1];
    const float* ts    = (const float*)d_in[2];
    const float* W1    = (const float*)d_in[3];
    const float* b1    = (const float*)d_in[4];
    const float* W2    = (const float*)d_in[5];
    const float* b2    = (const float*)d_in[6];
    const float* W3    = (const float*)d_in[7];
    const float* b3    = (const float*)d_in[8];
    float* out = (float*)d_out;

    ode_rk2_kernel<<<1, 64>>>(x0, treat, ts, W1, b1, W2, b2, W3, b3, out);
}

// round 6
// speedup vs baseline: 2.1952x; 1.1201x over previous
#include <cuda_runtime.h>
#include <cuda_bf16.h>

// Counterfactual neural-ODE, midpoint RK2 per ts-segment, run in layer-1
// PRE-ACTIVATION space: with M = W3@W1 (64x64) precomputed in-kernel and
// A[t] = (W1^T x)[t], each RHS eval is   h1=tanh(A+be) -> bar -> h2 ->
// bar -> g = M-dot(h2);  A updates directly from g. 2 barriers/eval.
// Trajectory x is reconstructed off the critical path via half-K W3
// partials combined at the next segment's first barrier.
// R5 fix: p3b half-K partial loop covers all 32 k (q<8), not 16 (q<4).

typedef unsigned long long ull;

__device__ __forceinline__ ull pack2(float lo, float hi) {
    ull r; asm("mov.b64 %0, {%1, %2};" : "=l"(r) : "f"(lo), "f"(hi)); return r;
}
__device__ __forceinline__ ull addf2(ull a, ull b) {
    ull d; asm("add.rn.f32x2 %0, %1, %2;" : "=l"(d) : "l"(a), "l"(b)); return d;
}
__device__ __forceinline__ void ffma2(ull& d, ull a, ull b) {
    asm("fma.rn.f32x2 %0, %1, %2, %3;" : "=l"(d) : "l"(a), "l"(b), "l"(d));
}
__device__ __forceinline__ float hsum(ull v) {
    float lo, hi; asm("mov.b64 {%0, %1}, %2;" : "=f"(lo), "=f"(hi) : "l"(v));
    return lo + hi;
}
__device__ __forceinline__ float hsum4(ull a, ull b, ull c, ull d) {
    return hsum(addf2(addf2(a, b), addf2(c, d)));
}

__device__ __forceinline__ float ftanh(float x) {
    // tanh(x) = 1 - 2/(exp(2x)+1); MUFU.EX2 + MUFU.RCP, ~1e-6 accuracy.
    float e = __expf(2.0f * x);
    return 1.0f - __fdividef(2.0f, e + 1.0f);
}

__global__ void __launch_bounds__(64, 1)
ode_fused_kernel(const float* __restrict__ x0,
                 const float* __restrict__ treat,   // [100,4]
                 const float* __restrict__ ts,      // [100]
                 const float* __restrict__ W1,      // [36,64]
                 const float* __restrict__ b1,      // [64]
                 const float* __restrict__ W2,      // [64,64]
                 const float* __restrict__ b2,      // [64]
                 const float* __restrict__ W3,      // [64,32]
                 const float* __restrict__ b3,      // [32]
                 float* __restrict__ out)           // [100,32]
{
    __shared__ __align__(16) float h1b[64];
    __shared__ __align__(16) float h2b[64];
    __shared__ __align__(16) float p3b[64];     // half-K W3 partials
    __shared__ __align__(16) float w3s[2048];   // W3 staged for M precompute
    __shared__ float trb[400];
    __shared__ float tsb[104];

    const int t  = threadIdx.x;
    const int i3 = t & 31;
    const int kh = t >> 5;

    for (int j = t; j < 2048; j += 64) w3s[j] = W3[j];
    for (int j = t; j < 400;  j += 64) trb[j] = treat[j];
    for (int j = t; j < 100;  j += 64) tsb[j] = ts[j];
    if (t < 32) { h1b[t] = x0[t]; h2b[t] = b3[t]; out[t] = x0[t]; }
    __syncthreads();

    // ---- W1 column t ----
    ull w1p[16];
#pragma unroll
    for (int j = 0; j < 16; ++j)
        w1p[j] = pack2(W1[(2 * j) * 64 + t], W1[(2 * j + 1) * 64 + t]);
    const float w1t0 = W1[32 * 64 + t], w1t1 = W1[33 * 64 + t];
    const float w1t2 = W1[34 * 64 + t], w1t3 = W1[35 * 64 + t];
    const float bb1 = b1[t];
    const float bb2 = b2[t];
    const float bb3 = (t < 32) ? b3[t] : 0.0f;

    // ---- A0 = W1col . x0  and  c3 = W1col . b3 ----
    float A, c3;
    {
        ull a0 = 0, a1 = 0, a2 = 0, a3 = 0, e0 = 0, e1 = 0, e2 = 0, e3 = 0;
        const ulonglong2* sx = (const ulonglong2*)h1b;
        const ulonglong2* sb = (const ulonglong2*)h2b;
#pragma unroll
        for (int q = 0; q < 4; ++q) {
            ulonglong2 vx0 = sx[2 * q], vx1 = sx[2 * q + 1];
            ulonglong2 vb0 = sb[2 * q], vb1 = sb[2 * q + 1];
            ffma2(a0, vx0.x, w1p[4 * q + 0]); ffma2(a1, vx0.y, w1p[4 * q + 1]);
            ffma2(a2, vx1.x, w1p[4 * q + 2]); ffma2(a3, vx1.y, w1p[4 * q + 3]);
            ffma2(e0, vb0.x, w1p[4 * q + 0]); ffma2(e1, vb0.y, w1p[4 * q + 1]);
            ffma2(e2, vb1.x, w1p[4 * q + 2]); ffma2(e3, vb1.y, w1p[4 * q + 3]);
        }
        A  = hsum4(a0, a1, a2, a3);
        c3 = hsum4(e0, e1, e2, e3);
    }

    // ---- M column t: Mp[j] = (M[2j,t], M[2j+1,t]),  M[k,t] = W3[k,:].W1[:,t]
    ull Mp[32];
#pragma unroll
    for (int j = 0; j < 32; ++j) {
        ull m0 = 0, m1 = 0, n0 = 0, n1 = 0;
        const ulonglong2* r0 = (const ulonglong2*)(w3s + (2 * j) * 32);
        const ulonglong2* r1 = (const ulonglong2*)(w3s + (2 * j + 1) * 32);
#pragma unroll
        for (int q = 0; q < 4; ++q) {
            ulonglong2 u0 = r0[2 * q], u1 = r0[2 * q + 1];
            ulonglong2 v0 = r1[2 * q], v1 = r1[2 * q + 1];
            ffma2(m0, u0.x, w1p[4 * q + 0]); ffma2(m1, u0.y, w1p[4 * q + 1]);
            ffma2(m0, u1.x, w1p[4 * q + 2]); ffma2(m1, u1.y, w1p[4 * q + 3]);
            ffma2(n0, v0.x, w1p[4 * q + 0]); ffma2(n1, v0.y, w1p[4 * q + 1]);
            ffma2(n0, v1.x, w1p[4 * q + 2]); ffma2(n1, v1.y, w1p[4 * q + 3]);
        }
        Mp[j] = pack2(hsum(addf2(m0, m1)), hsum(addf2(n0, n1)));
    }

    // ---- W2 column t, and this thread's half-K W3 column (output lane i3) --
    ull w2p[32];
#pragma unroll
    for (int j = 0; j < 32; ++j)
        w2p[j] = pack2(W2[(2 * j) * 64 + t], W2[(2 * j + 1) * 64 + t]);
    ull w3h[16];
#pragma unroll
    for (int j = 0; j < 16; ++j)
        w3h[j] = pack2(W3[(kh * 32 + 2 * j) * 32 + i3],
                       W3[(kh * 32 + 2 * j + 1) * 32 + i3]);

    float x = (t < 32) ? x0[t] : 0.0f;
    __syncthreads();   // all prologue SMEM reads done before eval overwrites

    float hprev = 0.0f;

#pragma unroll 1
    for (int seg = 0; seg < 99; ++seg) {
        const float h = tsb[seg + 1] - tsb[seg];
        const float ta0 = trb[4 * seg + 0], ta1 = trb[4 * seg + 1];
        const float ta2 = trb[4 * seg + 2], ta3 = trb[4 * seg + 3];
        const float c0 = fmaf(w1t0, ta0, fmaf(w1t1, ta1, fmaf(w1t2, ta2, w1t3 * ta3)));
        const float c1 = fmaf(w1t0, trb[4 * seg + 4] - ta0,
                         fmaf(w1t1, trb[4 * seg + 5] - ta1,
                         fmaf(w1t2, trb[4 * seg + 6] - ta2,
                               w1t3 * (trb[4 * seg + 7] - ta3))));
        const float be1 = bb1 + c0;
        const float be2 = fmaf(0.5f, c1, be1);

        // ================= eval 1 =================
        h1b[t] = ftanh(A + be1);
        __syncthreads();                                   // h1 ready
        // finalize previous segment's output (off critical path)
        if (seg > 0 && t < 32) {
            const float kv = p3b[t] + p3b[t + 32] + bb3;
            x = fmaf(hprev, kv, x);
            out[seg * 32 + t] = x;
        }
        {   // layer 2
            ull q0 = pack2(bb2, 0.0f), q1 = 0, q2 = 0, q3 = 0;
            const ulonglong2* hv = (const ulonglong2*)h1b;
#pragma unroll
            for (int q = 0; q < 8; ++q) {
                ulonglong2 v0 = hv[2 * q], v1 = hv[2 * q + 1];
                ffma2(q0, v0.x, w2p[4 * q + 0]); ffma2(q1, v0.y, w2p[4 * q + 1]);
                ffma2(q2, v1.x, w2p[4 * q + 2]); ffma2(q3, v1.y, w2p[4 * q + 3]);
            }
            h2b[t] = ftanh(hsum4(q0, q1, q2, q3));
        }
        __syncthreads();                                   // h2 ready
        float g1;
        {   // fused (layer3 -> layer1) dot: g1 = M[:,t] . h2
            ull d0 = 0, d1 = 0, d2 = 0, d3 = 0;
            const ulonglong2* gv = (const ulonglong2*)h2b;
#pragma unroll
            for (int q = 0; q < 8; ++q) {
                ulonglong2 v0 = gv[2 * q], v1 = gv[2 * q + 1];
                ffma2(d0, v0.x, Mp[4 * q + 0]); ffma2(d1, v0.y, Mp[4 * q + 1]);
                ffma2(d2, v1.x, Mp[4 * q + 2]); ffma2(d3, v1.y, Mp[4 * q + 3]);
            }
            g1 = hsum4(d0, d1, d2, d3);
        }
        const float Amid = fmaf(0.5f * h, g1 + c3, A);

        // ================= eval 2 =================
        h1b[t] = ftanh(Amid + be2);
        __syncthreads();                                   // h1 ready
        {   // layer 2
            ull q0 = pack2(bb2, 0.0f), q1 = 0, q2 = 0, q3 = 0;
            const ulonglong2* hv = (const ulonglong2*)h1b;
#pragma unroll
            for (int q = 0; q < 8; ++q) {
                ulonglong2 v0 = hv[2 * q], v1 = hv[2 * q + 1];
                ffma2(q0, v0.x, w2p[4 * q + 0]); ffma2(q1, v0.y, w2p[4 * q + 1]);
                ffma2(q2, v1.x, w2p[4 * q + 2]); ffma2(q3, v1.y, w2p[4 * q + 3]);
            }
            h2b[t] = ftanh(hsum4(q0, q1, q2, q3));
        }
        __syncthreads();                                   // h2 ready
        float g2;
        {
            ull d0 = 0, d1 = 0, d2 = 0, d3 = 0;
            ull p0 = 0, p1 = 0;
            const ulonglong2* gv = (const ulonglong2*)h2b;
#pragma unroll
            for (int q = 0; q < 8; ++q) {
                ulonglong2 v0 = gv[2 * q], v1 = gv[2 * q + 1];
                ffma2(d0, v0.x, Mp[4 * q + 0]); ffma2(d1, v0.y, Mp[4 * q + 1]);
                ffma2(d2, v1.x, Mp[4 * q + 2]); ffma2(d3, v1.y, Mp[4 * q + 3]);
            }
            // half-K W3 partial for trajectory output (off critical path).
            // pv[q] = 4 floats; q<8 covers all 32 k of this thread's half.
            const ulonglong2* pv = (const ulonglong2*)(h2b + kh * 32);
#pragma unroll
            for (int q = 0; q < 8; ++q) {
                ulonglong2 v = pv[q];
                ffma2(p0, v.x, w3h[2 * q]);
                ffma2(p1, v.y, w3h[2 * q + 1]);
            }
            p3b[t] = hsum(addf2(p0, p1));
            g2 = hsum4(d0, d1, d2, d3);
        }
        A = fmaf(h, g2 + c3, A);
        hprev = h;
    }

    __syncthreads();   // publish last segment's partials
    if (t < 32) {
        const float kv = p3b[t] + p3b[t + 32] + bb3;
        out[99 * 32 + t] = fmaf(hprev, kv, x);
    }
}

extern "C" void kernel_launch(void* const* d_in, const int* in_sizes, int n_in,
                              void* d_out, int out_size) {
    const float* x0    = (const float*)d_in[0];
    const float* treat = (const float*)d_in[1];
    const float* ts    = (const float*)d_in[2];
    const float* W1    = (const float*)d_in[3];
    const float* b1    = (const float*)d_in[4];
    const float* W2    = (const float*)d_in[5];
    const float* b2    = (const float*)d_in[6];
    const float* W3    = (const float*)d_in[7];
    const float* b3    = (const float*)d_in[8];
    float* out = (float*)d_out;

    ode_fused_kernel<<<1, 64>>>(x0, treat, ts, W1, b1, W2, b2, W3, b3, out);
}

// round 8
// speedup vs baseline: 2.5149x; 1.1456x over previous
#include <cuda_runtime.h>
#include <cuda_bf16.h>

// Counterfactual neural-ODE, midpoint RK2 per ts-segment, run in layer-1
// PRE-ACTIVATION space: with M = W3@W1 (64x64) precomputed in-kernel and
// A[t] = (W1^T x)[t], each eval is  h1=tanh(A+be) -> bar -> h2 -> bar ->
// g = M-dot(h2);  A updates directly from g. 2 barriers/eval.
// R7: trajectory W3 weights moved to SMEM transpose (kills register spills,
// regs were at the 255 cap), hardware tanh.approx, vectorized treatment bias.

typedef unsigned long long ull;

__device__ __forceinline__ ull pack2(float lo, float hi) {
    ull r; asm("mov.b64 %0, {%1, %2};" : "=l"(r) : "f"(lo), "f"(hi)); return r;
}
__device__ __forceinline__ ull addf2(ull a, ull b) {
    ull d; asm("add.rn.f32x2 %0, %1, %2;" : "=l"(d) : "l"(a), "l"(b)); return d;
}
__device__ __forceinline__ void ffma2(ull& d, ull a, ull b) {
    asm("fma.rn.f32x2 %0, %1, %2, %3;" : "=l"(d) : "l"(a), "l"(b), "l"(d));
}
__device__ __forceinline__ float hsum(ull v) {
    float lo, hi; asm("mov.b64 {%0, %1}, %2;" : "=f"(lo), "=f"(hi) : "l"(v));
    return lo + hi;
}
__device__ __forceinline__ float hsum4(ull a, ull b, ull c, ull d) {
    return hsum(addf2(addf2(a, b), addf2(c, d)));
}
__device__ __forceinline__ float ftanh(float x) {
    float r; asm("tanh.approx.f32 %0, %1;" : "=f"(r) : "f"(x)); return r;
}

__global__ void __launch_bounds__(64, 1)
ode_fused_kernel(const float* __restrict__ x0,
                 const float* __restrict__ treat,   // [100,4]
                 const float* __restrict__ ts,      // [100]
                 const float* __restrict__ W1,      // [36,64]
                 const float* __restrict__ b1,      // [64]
                 const float* __restrict__ W2,      // [64,64]
                 const float* __restrict__ b2,      // [64]
                 const float* __restrict__ W3,      // [64,32]
                 const float* __restrict__ b3,      // [32]
                 float* __restrict__ out)           // [100,32]
{
    __shared__ __align__(16) float h1b[64];
    __shared__ __align__(16) float h2b[64];
    __shared__ __align__(16) float p3b[64];       // half-K W3 partials
    __shared__ __align__(16) float w3s[2048];     // W3 staged (M precompute)
    __shared__ __align__(16) float w3t[32 * 68];  // W3 transposed+padded
    __shared__ __align__(16) float trb[400];
    __shared__ __align__(16) float trd[400];      // per-seg treatment deltas
    __shared__ float tsb[104];

    const int t  = threadIdx.x;
    const int i3 = t & 31;
    const int kh = t >> 5;

    for (int j = t; j < 2048; j += 64) w3s[j] = W3[j];
    for (int j = t; j < 400;  j += 64) trb[j] = treat[j];
    for (int j = t; j < 100;  j += 64) tsb[j] = ts[j];
    if (t < 32) { h1b[t] = x0[t]; h2b[t] = b3[t]; out[t] = x0[t]; }
    __syncthreads();

    // ---- W1 column t ----
    ull w1p[16];
#pragma unroll
    for (int j = 0; j < 16; ++j)
        w1p[j] = pack2(W1[(2 * j) * 64 + t], W1[(2 * j + 1) * 64 + t]);
    const ull w1ta = pack2(W1[32 * 64 + t], W1[33 * 64 + t]);
    const ull w1tb = pack2(W1[34 * 64 + t], W1[35 * 64 + t]);
    const float bb1 = b1[t];
    const float bb2 = b2[t];
    const float bb3 = (t < 32) ? b3[t] : 0.0f;

    // ---- A0 = W1col . x0  and  c3 = W1col . b3 ----
    float A, c3;
    {
        ull a0 = 0, a1 = 0, a2 = 0, a3 = 0, e0 = 0, e1 = 0, e2 = 0, e3 = 0;
        const ulonglong2* sx = (const ulonglong2*)h1b;
        const ulonglong2* sb = (const ulonglong2*)h2b;
#pragma unroll
        for (int q = 0; q < 4; ++q) {
            ulonglong2 vx0 = sx[2 * q], vx1 = sx[2 * q + 1];
            ulonglong2 vb0 = sb[2 * q], vb1 = sb[2 * q + 1];
            ffma2(a0, vx0.x, w1p[4 * q + 0]); ffma2(a1, vx0.y, w1p[4 * q + 1]);
            ffma2(a2, vx1.x, w1p[4 * q + 2]); ffma2(a3, vx1.y, w1p[4 * q + 3]);
            ffma2(e0, vb0.x, w1p[4 * q + 0]); ffma2(e1, vb0.y, w1p[4 * q + 1]);
            ffma2(e2, vb1.x, w1p[4 * q + 2]); ffma2(e3, vb1.y, w1p[4 * q + 3]);
        }
        A  = hsum4(a0, a1, a2, a3);
        c3 = hsum4(e0, e1, e2, e3);
    }

    // ---- M column t: Mp[j] = (M[2j,t], M[2j+1,t]),  M[k,t] = W3[k,:].W1[:,t]
    ull Mp[32];
#pragma unroll
    for (int j = 0; j < 32; ++j) {
        ull m0 = 0, m1 = 0, n0 = 0, n1 = 0;
        const ulonglong2* r0 = (const ulonglong2*)(w3s + (2 * j) * 32);
        const ulonglong2* r1 = (const ulonglong2*)(w3s + (2 * j + 1) * 32);
#pragma unroll
        for (int q = 0; q < 4; ++q) {
            ulonglong2 u0 = r0[2 * q], u1 = r0[2 * q + 1];
            ulonglong2 v0 = r1[2 * q], v1 = r1[2 * q + 1];
            ffma2(m0, u0.x, w1p[4 * q + 0]); ffma2(m1, u0.y, w1p[4 * q + 1]);
            ffma2(m0, u1.x, w1p[4 * q + 2]); ffma2(m1, u1.y, w1p[4 * q + 3]);
            ffma2(n0, v0.x, w1p[4 * q + 0]); ffma2(n1, v0.y, w1p[4 * q + 1]);
            ffma2(n0, v1.x, w1p[4 * q + 2]); ffma2(n1, v1.y, w1p[4 * q + 3]);
        }
        Mp[j] = pack2(hsum(addf2(m0, m1)), hsum(addf2(n0, n1)));
    }

    // ---- W2 column t (registers) ----
    ull w2p[32];
#pragma unroll
    for (int j = 0; j < 32; ++j)
        w2p[j] = pack2(W2[(2 * j) * 64 + t], W2[(2 * j + 1) * 64 + t]);

    // ---- W3 transpose into SMEM (trajectory partials read it via LDS) ----
    for (int j = t; j < 2048; j += 64) {
        int k = j >> 5, i = j & 31;
        w3t[i * 68 + k] = w3s[j];
    }
    // per-segment treatment deltas
    for (int j = t; j < 396; j += 64) trd[j] = trb[j + 4] - trb[j];

    float x = (t < 32) ? x0[t] : 0.0f;
    __syncthreads();   // prologue SMEM reads/writes done before evals

    const ulonglong2* pw = (const ulonglong2*)(w3t + i3 * 68 + kh * 32);
    float hprev = 0.0f;

#pragma unroll 1
    for (int seg = 0; seg < 99; ++seg) {
        const float h = tsb[seg + 1] - tsb[seg];
        const ulonglong2 vA = *(const ulonglong2*)(trb + 4 * seg);
        const ulonglong2 vD = *(const ulonglong2*)(trd + 4 * seg);
        ull u0 = 0, u1 = 0;
        ffma2(u0, vA.x, w1ta); ffma2(u0, vA.y, w1tb);
        ffma2(u1, vD.x, w1ta); ffma2(u1, vD.y, w1tb);
        const float be1 = bb1 + hsum(u0);
        const float be2 = fmaf(0.5f, hsum(u1), be1);

        // ================= eval 1 =================
        h1b[t] = ftanh(A + be1);
        __syncthreads();                                   // h1 ready
        // finalize previous segment's output (off critical path)
        if (seg > 0 && t < 32) {
            const float kv = p3b[t] + p3b[t + 32] + bb3;
            x = fmaf(hprev, kv, x);
            out[seg * 32 + t] = x;
        }
        {   // layer 2
            ull q0 = pack2(bb2, 0.0f), q1 = 0, q2 = 0, q3 = 0;
            const ulonglong2* hv = (const ulonglong2*)h1b;
#pragma unroll
            for (int q = 0; q < 8; ++q) {
                ulonglong2 v0 = hv[2 * q], v1 = hv[2 * q + 1];
                ffma2(q0, v0.x, w2p[4 * q + 0]); ffma2(q1, v0.y, w2p[4 * q + 1]);
                ffma2(q2, v1.x, w2p[4 * q + 2]); ffma2(q3, v1.y, w2p[4 * q + 3]);
            }
            h2b[t] = ftanh(hsum4(q0, q1, q2, q3));
        }
        __syncthreads();                                   // h2 ready
        float g1;
        {   // fused (layer3 -> layer1) dot: g1 = M[:,t] . h2
            ull d0 = 0, d1 = 0, d2 = 0, d3 = 0;
            const ulonglong2* gv = (const ulonglong2*)h2b;
#pragma unroll
            for (int q = 0; q < 8; ++q) {
                ulonglong2 v0 = gv[2 * q], v1 = gv[2 * q + 1];
                ffma2(d0, v0.x, Mp[4 * q + 0]); ffma2(d1, v0.y, Mp[4 * q + 1]);
                ffma2(d2, v1.x, Mp[4 * q + 2]); ffma2(d3, v1.y, Mp[4 * q + 3]);
            }
            g1 = hsum4(d0, d1, d2, d3);
        }
        const float Amid = fmaf(0.5f * h, g1 + c3, A);

        // ================= eval 2 =================
        h1b[t] = ftanh(Amid + be2);
        __syncthreads();                                   // h1 ready
        {   // layer 2
            ull q0 = pack2(bb2, 0.0f), q1 = 0, q2 = 0, q3 = 0;
            const ulonglong2* hv = (const ulonglong2*)h1b;
#pragma unroll
            for (int q = 0; q < 8; ++q) {
                ulonglong2 v0 = hv[2 * q], v1 = hv[2 * q + 1];
                ffma2(q0, v0.x, w2p[4 * q + 0]); ffma2(q1, v0.y, w2p[4 * q + 1]);
                ffma2(q2, v1.x, w2p[4 * q + 2]); ffma2(q3, v1.y, w2p[4 * q + 3]);
            }
            h2b[t] = ftanh(hsum4(q0, q1, q2, q3));
        }
        __syncthreads();                                   // h2 ready
        float g2;
        {
            ull d0 = 0, d1 = 0, d2 = 0, d3 = 0;
            ull p0 = 0, p1 = 0;
            const ulonglong2* gv = (const ulonglong2*)h2b;
#pragma unroll
            for (int q = 0; q < 8; ++q) {
                ulonglong2 v0 = gv[2 * q], v1 = gv[2 * q + 1];
                ffma2(d0, v0.x, Mp[4 * q + 0]); ffma2(d1, v0.y, Mp[4 * q + 1]);
                ffma2(d2, v1.x, Mp[4 * q + 2]); ffma2(d3, v1.y, Mp[4 * q + 3]);
            }
            // half-K W3 partial for trajectory output (weights via SMEM,
            // off critical path): covers k in [kh*32, kh*32+32)
            const ulonglong2* ph = (const ulonglong2*)(h2b + kh * 32);
#pragma unroll
            for (int q = 0; q < 8; ++q) {
                ulonglong2 wv = pw[q], hv = ph[q];
                ffma2(p0, hv.x, wv.x);
                ffma2(p1, hv.y, wv.y);
            }
            p3b[t] = hsum(addf2(p0, p1));
            g2 = hsum4(d0, d1, d2, d3);
        }
        A = fmaf(h, g2 + c3, A);
        hprev = h;
    }

    __syncthreads();   // publish last segment's partials
    if (t < 32) {
        const float kv = p3b[t] + p3b[t + 32] + bb3;
        out[99 * 32 + t] = fmaf(hprev, kv, x);
    }
}

extern "C" void kernel_launch(void* const* d_in, const int* in_sizes, int n_in,
                              void* d_out, int out_size) {
    const float* x0    = (const float*)d_in[0];
    const float* treat = (const float*)d_in[1];
    const float* ts    = (const float*)d_in[2];
    const float* W1    = (const float*)d_in[3];
    const float* b1    = (const float*)d_in[4];
    const float* W2    = (const float*)d_in[5];
    const float* b2    = (const float*)d_in[6];
    const float* W3    = (const float*)d_in[7];
    const float* b3    = (const float*)d_in[8];
    float* out = (float*)d_out;

    ode_fused_kernel<<<1, 64>>>(x0, treat, ts, W1, b1, W2, b2, W3, b3, out);
}

// round 9
// speedup vs baseline: 3.2345x; 1.2861x over previous
#include <cuda_runtime.h>
#include <cuda_bf16.h>

// Counterfactual neural-ODE in layer-1 PRE-ACTIVATION space (M = W3@W1
// precomputed in-kernel, state A = W1^T x). R9: midpoint RK2 over DOUBLE
// ts-segments (49 double steps + 1 single, 100 RHS evals total). Stage-2
// treatment uses the exact piecewise-linear time-average (tr0+2tr1+tr2)/4,
// which removes the forcing-aliasing error from the interior kink. Odd-knot
// outputs are reconstructed off the critical path as x + (H/4)(k1+k2) via
// two W3 half-K partial buffers (p3a from eval1, p3b from eval2).

typedef unsigned long long ull;

__device__ __forceinline__ ull pack2(float lo, float hi) {
    ull r; asm("mov.b64 %0, {%1, %2};" : "=l"(r) : "f"(lo), "f"(hi)); return r;
}
__device__ __forceinline__ ull addf2(ull a, ull b) {
    ull d; asm("add.rn.f32x2 %0, %1, %2;" : "=l"(d) : "l"(a), "l"(b)); return d;
}
__device__ __forceinline__ void ffma2(ull& d, ull a, ull b) {
    asm("fma.rn.f32x2 %0, %1, %2, %3;" : "=l"(d) : "l"(a), "l"(b), "l"(d));
}
__device__ __forceinline__ float hsum(ull v) {
    float lo, hi; asm("mov.b64 {%0, %1}, %2;" : "=f"(lo), "=f"(hi) : "l"(v));
    return lo + hi;
}
__device__ __forceinline__ float hsum4(ull a, ull b, ull c, ull d) {
    return hsum(addf2(addf2(a, b), addf2(c, d)));
}
__device__ __forceinline__ float ftanh(float x) {
    float r; asm("tanh.approx.f32 %0, %1;" : "=f"(r) : "f"(x)); return r;
}

__global__ void __launch_bounds__(64, 1)
ode_fused_kernel(const float* __restrict__ x0,
                 const float* __restrict__ treat,   // [100,4]
                 const float* __restrict__ ts,      // [100]
                 const float* __restrict__ W1,      // [36,64]
                 const float* __restrict__ b1,      // [64]
                 const float* __restrict__ W2,      // [64,64]
                 const float* __restrict__ b2,      // [64]
                 const float* __restrict__ W3,      // [64,32]
                 const float* __restrict__ b3,      // [32]
                 float* __restrict__ out)           // [100,32]
{
    __shared__ __align__(16) float h1b[64];
    __shared__ __align__(16) float h2b[64];
    __shared__ __align__(16) float p3a[64];       // eval-1 W3 half-K partials
    __shared__ __align__(16) float p3b[64];       // eval-2 W3 half-K partials
    __shared__ __align__(16) float w3s[2048];     // W3 staged (prologue)
    __shared__ __align__(16) float w3t[32 * 68];  // W3 transposed+padded
    __shared__ __align__(16) float trb[400];
    __shared__ __align__(16) float sArr[100 * 64]; // per-thread treatment dots
    __shared__ float tsb[104];

    const int t  = threadIdx.x;
    const int i3 = t & 31;
    const int kh = t >> 5;

    for (int j = t; j < 2048; j += 64) w3s[j] = W3[j];
    for (int j = t; j < 400;  j += 64) trb[j] = treat[j];
    for (int j = t; j < 100;  j += 64) tsb[j] = ts[j];
    if (t < 32) { h1b[t] = x0[t]; h2b[t] = b3[t]; out[t] = x0[t]; }
    __syncthreads();

    // ---- W1 column t ----
    ull w1p[16];
#pragma unroll
    for (int j = 0; j < 16; ++j)
        w1p[j] = pack2(W1[(2 * j) * 64 + t], W1[(2 * j + 1) * 64 + t]);
    const ull w1ta = pack2(W1[32 * 64 + t], W1[33 * 64 + t]);
    const ull w1tb = pack2(W1[34 * 64 + t], W1[35 * 64 + t]);
    const float bb1 = b1[t];
    const float bb2 = b2[t];
    const float bb3 = (t < 32) ? b3[t] : 0.0f;

    // ---- A0 = W1col . x0  and  c3 = W1col . b3 ----
    float A, c3;
    {
        ull a0 = 0, a1 = 0, a2 = 0, a3 = 0, e0 = 0, e1 = 0, e2 = 0, e3 = 0;
        const ulonglong2* sx = (const ulonglong2*)h1b;
        const ulonglong2* sb = (const ulonglong2*)h2b;
#pragma unroll
        for (int q = 0; q < 4; ++q) {
            ulonglong2 vx0 = sx[2 * q], vx1 = sx[2 * q + 1];
            ulonglong2 vb0 = sb[2 * q], vb1 = sb[2 * q + 1];
            ffma2(a0, vx0.x, w1p[4 * q + 0]); ffma2(a1, vx0.y, w1p[4 * q + 1]);
            ffma2(a2, vx1.x, w1p[4 * q + 2]); ffma2(a3, vx1.y, w1p[4 * q + 3]);
            ffma2(e0, vb0.x, w1p[4 * q + 0]); ffma2(e1, vb0.y, w1p[4 * q + 1]);
            ffma2(e2, vb1.x, w1p[4 * q + 2]); ffma2(e3, vb1.y, w1p[4 * q + 3]);
        }
        A  = hsum4(a0, a1, a2, a3);
        c3 = hsum4(e0, e1, e2, e3);
    }

    // ---- M column t: Mp[j] = (M[2j,t], M[2j+1,t]),  M[k,t] = W3[k,:].W1[:,t]
    ull Mp[32];
#pragma unroll
    for (int j = 0; j < 32; ++j) {
        ull m0 = 0, m1 = 0, n0 = 0, n1 = 0;
        const ulonglong2* r0 = (const ulonglong2*)(w3s + (2 * j) * 32);
        const ulonglong2* r1 = (const ulonglong2*)(w3s + (2 * j + 1) * 32);
#pragma unroll
        for (int q = 0; q < 4; ++q) {
            ulonglong2 u0 = r0[2 * q], u1 = r0[2 * q + 1];
            ulonglong2 v0 = r1[2 * q], v1 = r1[2 * q + 1];
            ffma2(m0, u0.x, w1p[4 * q + 0]); ffma2(m1, u0.y, w1p[4 * q + 1]);
            ffma2(m0, u1.x, w1p[4 * q + 2]); ffma2(m1, u1.y, w1p[4 * q + 3]);
            ffma2(n0, v0.x, w1p[4 * q + 0]); ffma2(n1, v0.y, w1p[4 * q + 1]);
            ffma2(n0, v1.x, w1p[4 * q + 2]); ffma2(n1, v1.y, w1p[4 * q + 3]);
        }
        Mp[j] = pack2(hsum(addf2(m0, m1)), hsum(addf2(n0, n1)));
    }

    // ---- W2 column t (registers) ----
    ull w2p[32];
#pragma unroll
    for (int j = 0; j < 32; ++j)
        w2p[j] = pack2(W2[(2 * j) * 64 + t], W2[(2 * j + 1) * 64 + t]);

    // ---- W3 transpose into SMEM (trajectory partials read it via LDS) ----
    for (int j = t; j < 2048; j += 64) {
        int k = j >> 5, i = j & 31;
        w3t[i * 68 + k] = w3s[j];
    }

    // ---- per-thread treatment dots: sArr[j][t] = W1_tr[:,t] . tr_j ----
#pragma unroll 4
    for (int j = 0; j < 100; ++j) {
        ull u = 0;
        const ulonglong2 v = *(const ulonglong2*)(trb + 4 * j);
        ffma2(u, v.x, w1ta); ffma2(u, v.y, w1tb);
        sArr[j * 64 + t] = hsum(u);
    }

    float x = (t < 32) ? x0[t] : 0.0f;
    __syncthreads();   // prologue SMEM writes published

    const ulonglong2* pw = (const ulonglong2*)(w3t + i3 * 68 + kh * 32);

    // -------- reusable phases --------
    auto layer2 = [&]() {
        ull q0 = pack2(bb2, 0.0f), q1 = 0, q2 = 0, q3 = 0;
        const ulonglong2* hv = (const ulonglong2*)h1b;
#pragma unroll
        for (int q = 0; q < 8; ++q) {
            ulonglong2 v0 = hv[2 * q], v1 = hv[2 * q + 1];
            ffma2(q0, v0.x, w2p[4 * q + 0]); ffma2(q1, v0.y, w2p[4 * q + 1]);
            ffma2(q2, v1.x, w2p[4 * q + 2]); ffma2(q3, v1.y, w2p[4 * q + 3]);
        }
        h2b[t] = ftanh(hsum4(q0, q1, q2, q3));
    };
    auto gdot = [&]() -> float {     // g = M[:,t] . h2
        ull d0 = 0, d1 = 0, d2 = 0, d3 = 0;
        const ulonglong2* gv = (const ulonglong2*)h2b;
#pragma unroll
        for (int q = 0; q < 8; ++q) {
            ulonglong2 v0 = gv[2 * q], v1 = gv[2 * q + 1];
            ffma2(d0, v0.x, Mp[4 * q + 0]); ffma2(d1, v0.y, Mp[4 * q + 1]);
            ffma2(d2, v1.x, Mp[4 * q + 2]); ffma2(d3, v1.y, Mp[4 * q + 3]);
        }
        return hsum4(d0, d1, d2, d3);
    };
    auto pdot = [&](float* dst) {    // W3 half-K trajectory partial
        ull p0 = 0, p1 = 0;
        const ulonglong2* ph = (const ulonglong2*)(h2b + kh * 32);
#pragma unroll
        for (int q = 0; q < 8; ++q) {
            ulonglong2 wv = pw[q], hv = ph[q];
            ffma2(p0, hv.x, wv.x);
            ffma2(p1, hv.y, wv.y);
        }
        dst[t] = hsum(addf2(p0, p1));
    };

    float Hp = 0.0f;

#pragma unroll 1
    for (int j = 0; j < 49; ++j) {
        const int base = 2 * j;
        const float H  = tsb[base + 2] - tsb[base];
        const float s0 = sArr[(base + 0) * 64 + t];
        const float s1 = sArr[(base + 1) * 64 + t];
        const float s2 = sArr[(base + 2) * 64 + t];
        const float be1 = bb1 + s0;
        // stage-2 bias: exact time-average of the piecewise-linear treatment
        const float beM = bb1 + 0.25f * (s0 + 2.0f * s1 + s2);

        // ================= eval 1 (k1 at t_base) =================
        h1b[t] = ftanh(A + be1);
        __syncthreads();                                   // h1 ready
        if (j > 0 && t < 32) {   // finalize previous double-step outputs
            const float pa = p3a[t] + p3a[t + 32];
            const float pb = p3b[t] + p3b[t + 32];
            out[(base - 1) * 32 + t] =
                fmaf(0.25f * Hp, pa + pb + 2.0f * bb3, x);  // odd knot
            x = fmaf(Hp, pb + bb3, x);                      // even knot
            out[base * 32 + t] = x;
        }
        layer2();
        __syncthreads();                                   // h2 ready
        pdot(p3a);                                         // k1 partial (off path)
        const float g1 = gdot();
        const float Amid = fmaf(0.5f * H, g1 + c3, A);

        // ================= eval 2 (k2 at midpoint) =================
        h1b[t] = ftanh(Amid + beM);
        __syncthreads();                                   // h1 ready
        layer2();
        __syncthreads();                                   // h2 ready
        pdot(p3b);                                         // k2 partial (off path)
        const float g2 = gdot();
        A = fmaf(H, g2 + c3, A);
        Hp = H;
    }

    // -------- outputs of last double step --------
    __syncthreads();
    if (t < 32) {
        const float pa = p3a[t] + p3a[t + 32];
        const float pb = p3b[t] + p3b[t + 32];
        out[97 * 32 + t] = fmaf(0.25f * Hp, pa + pb + 2.0f * bb3, x);
        x = fmaf(Hp, pb + bb3, x);
        out[98 * 32 + t] = x;
    }

    // -------- final single segment 98 -> 99 (plain midpoint RK2) --------
    {
        const float Hf  = tsb[99] - tsb[98];
        const float s98 = sArr[98 * 64 + t];
        const float s99 = sArr[99 * 64 + t];
        const float be1f = bb1 + s98;
        const float beMf = bb1 + 0.5f * (s98 + s99);

        h1b[t] = ftanh(A + be1f);
        __syncthreads();
        layer2();
        __syncthreads();
        const float g1 = gdot();
        const float Amid = fmaf(0.5f * Hf, g1 + c3, A);

        h1b[t] = ftanh(Amid + beMf);
        __syncthreads();
        layer2();
        __syncthreads();
        pdot(p3b);                       // only the trajectory partial needed
        __syncthreads();
        if (t < 32)
            out[99 * 32 + t] = fmaf(Hf, p3b[t] + p3b[t + 32] + bb3, x);
    }
}

extern "C" void kernel_launch(void* const* d_in, const int* in_sizes, int n_in,
                              void* d_out, int out_size) {
    const float* x0    = (const float*)d_in[0];
    const float* treat = (const float*)d_in[1];
    const float* ts    = (const float*)d_in[2];
    const float* W1    = (const float*)d_in[3];
    const float* b1    = (const float*)d_in[4];
    const float* W2    = (const float*)d_in[5];
    const float* b2    = (const float*)d_in[6];
    const float* W3    = (const float*)d_in[7];
    const float* b3    = (const float*)d_in[8];
    float* out = (float*)d_out;

    ode_fused_kernel<<<1, 64>>>(x0, treat, ts, W1, b1, W2, b2, W3, b3, out);
}

// round 10
// speedup vs baseline: 4.4939x; 1.3893x over previous
#include <cuda_runtime.h>
#include <cuda_bf16.h>

// Counterfactual neural-ODE in layer-1 PRE-ACTIVATION space (M = W3@W1
// precomputed in-kernel, state A = W1^T x). R10: midpoint RK2 over TRIPLE
// ts-segments (99 = 3*33, 66 RHS evals). Stage-2 treatment bias is the exact
// trapezoid mean over the step (kills forcing aliasing across the two
// interior kinks). Interior-knot outputs use the order-2 quadratic dense
// output q(th)=x+th*H*k1+th^2*H*(k2-k1). pdot/finalize issue into barrier
// shadows; gdot->A->tanh is the critical chain.

typedef unsigned long long ull;

__device__ __forceinline__ ull pack2(float lo, float hi) {
    ull r; asm("mov.b64 %0, {%1, %2};" : "=l"(r) : "f"(lo), "f"(hi)); return r;
}
__device__ __forceinline__ ull addf2(ull a, ull b) {
    ull d; asm("add.rn.f32x2 %0, %1, %2;" : "=l"(d) : "l"(a), "l"(b)); return d;
}
__device__ __forceinline__ void ffma2(ull& d, ull a, ull b) {
    asm("fma.rn.f32x2 %0, %1, %2, %3;" : "=l"(d) : "l"(a), "l"(b), "l"(d));
}
__device__ __forceinline__ float hsum(ull v) {
    float lo, hi; asm("mov.b64 {%0, %1}, %2;" : "=f"(lo), "=f"(hi) : "l"(v));
    return lo + hi;
}
__device__ __forceinline__ float hsum4(ull a, ull b, ull c, ull d) {
    return hsum(addf2(addf2(a, b), addf2(c, d)));
}
__device__ __forceinline__ float ftanh(float x) {
    float r; asm("tanh.approx.f32 %0, %1;" : "=f"(r) : "f"(x)); return r;
}

__global__ void __launch_bounds__(64, 1)
ode_fused_kernel(const float* __restrict__ x0,
                 const float* __restrict__ treat,   // [100,4]
                 const float* __restrict__ ts,      // [100]
                 const float* __restrict__ W1,      // [36,64]
                 const float* __restrict__ b1,      // [64]
                 const float* __restrict__ W2,      // [64,64]
                 const float* __restrict__ b2,      // [64]
                 const float* __restrict__ W3,      // [64,32]
                 const float* __restrict__ b3,      // [32]
                 float* __restrict__ out)           // [100,32]
{
    __shared__ __align__(16) float h1b[64];
    __shared__ __align__(16) float h2b[64];
    __shared__ __align__(16) float p3a[64];       // eval-1 (k1) W3 partials
    __shared__ __align__(16) float p3b[64];       // eval-2 (k2) W3 partials
    __shared__ __align__(16) float w3s[2048];     // W3 staged (prologue)
    __shared__ __align__(16) float w3t[32 * 68];  // W3 transposed+padded
    __shared__ __align__(16) float trb[400];
    __shared__ __align__(16) float sArr[100 * 64]; // per-thread treatment dots
    __shared__ float tsb[104];

    const int t  = threadIdx.x;
    const int i3 = t & 31;
    const int kh = t >> 5;

    for (int j = t; j < 2048; j += 64) w3s[j] = W3[j];
    for (int j = t; j < 400;  j += 64) trb[j] = treat[j];
    for (int j = t; j < 100;  j += 64) tsb[j] = ts[j];
    if (t < 32) { h1b[t] = x0[t]; h2b[t] = b3[t]; out[t] = x0[t]; }
    __syncthreads();

    // ---- W1 column t ----
    ull w1p[16];
#pragma unroll
    for (int j = 0; j < 16; ++j)
        w1p[j] = pack2(W1[(2 * j) * 64 + t], W1[(2 * j + 1) * 64 + t]);
    const ull w1ta = pack2(W1[32 * 64 + t], W1[33 * 64 + t]);
    const ull w1tb = pack2(W1[34 * 64 + t], W1[35 * 64 + t]);
    const float bb1 = b1[t];
    const float bb2 = b2[t];
    const float bb3 = (t < 32) ? b3[t] : 0.0f;

    // ---- A0 = W1col . x0  and  c3 = W1col . b3 ----
    float A, c3;
    {
        ull a0 = 0, a1 = 0, a2 = 0, a3 = 0, e0 = 0, e1 = 0, e2 = 0, e3 = 0;
        const ulonglong2* sx = (const ulonglong2*)h1b;
        const ulonglong2* sb = (const ulonglong2*)h2b;
#pragma unroll
        for (int q = 0; q < 4; ++q) {
            ulonglong2 vx0 = sx[2 * q], vx1 = sx[2 * q + 1];
            ulonglong2 vb0 = sb[2 * q], vb1 = sb[2 * q + 1];
            ffma2(a0, vx0.x, w1p[4 * q + 0]); ffma2(a1, vx0.y, w1p[4 * q + 1]);
            ffma2(a2, vx1.x, w1p[4 * q + 2]); ffma2(a3, vx1.y, w1p[4 * q + 3]);
            ffma2(e0, vb0.x, w1p[4 * q + 0]); ffma2(e1, vb0.y, w1p[4 * q + 1]);
            ffma2(e2, vb1.x, w1p[4 * q + 2]); ffma2(e3, vb1.y, w1p[4 * q + 3]);
        }
        A  = hsum4(a0, a1, a2, a3);
        c3 = hsum4(e0, e1, e2, e3);
    }

    // ---- M column t: Mp[j] = (M[2j,t], M[2j+1,t]),  M[k,t] = W3[k,:].W1[:,t]
    ull Mp[32];
#pragma unroll
    for (int j = 0; j < 32; ++j) {
        ull m0 = 0, m1 = 0, n0 = 0, n1 = 0;
        const ulonglong2* r0 = (const ulonglong2*)(w3s + (2 * j) * 32);
        const ulonglong2* r1 = (const ulonglong2*)(w3s + (2 * j + 1) * 32);
#pragma unroll
        for (int q = 0; q < 4; ++q) {
            ulonglong2 u0 = r0[2 * q], u1 = r0[2 * q + 1];
            ulonglong2 v0 = r1[2 * q], v1 = r1[2 * q + 1];
            ffma2(m0, u0.x, w1p[4 * q + 0]); ffma2(m1, u0.y, w1p[4 * q + 1]);
            ffma2(m0, u1.x, w1p[4 * q + 2]); ffma2(m1, u1.y, w1p[4 * q + 3]);
            ffma2(n0, v0.x, w1p[4 * q + 0]); ffma2(n1, v0.y, w1p[4 * q + 1]);
            ffma2(n0, v1.x, w1p[4 * q + 2]); ffma2(n1, v1.y, w1p[4 * q + 3]);
        }
        Mp[j] = pack2(hsum(addf2(m0, m1)), hsum(addf2(n0, n1)));
    }

    // ---- W2 column t (registers) ----
    ull w2p[32];
#pragma unroll
    for (int j = 0; j < 32; ++j)
        w2p[j] = pack2(W2[(2 * j) * 64 + t], W2[(2 * j + 1) * 64 + t]);

    // ---- W3 transpose into SMEM (trajectory partials read it via LDS) ----
    for (int j = t; j < 2048; j += 64) {
        int k = j >> 5, i = j & 31;
        w3t[i * 68 + k] = w3s[j];
    }

    // ---- per-thread treatment dots: sArr[j][t] = W1_tr[:,t] . tr_j ----
#pragma unroll 4
    for (int j = 0; j < 100; ++j) {
        ull u = 0;
        const ulonglong2 v = *(const ulonglong2*)(trb + 4 * j);
        ffma2(u, v.x, w1ta); ffma2(u, v.y, w1tb);
        sArr[j * 64 + t] = hsum(u);
    }

    float x = (t < 32) ? x0[t] : 0.0f;
    __syncthreads();   // prologue SMEM writes published

    const ulonglong2* pw = (const ulonglong2*)(w3t + i3 * 68 + kh * 32);

    // -------- reusable phases --------
    auto layer2 = [&]() {
        ull q0 = pack2(bb2, 0.0f), q1 = 0, q2 = 0, q3 = 0;
        const ulonglong2* hv = (const ulonglong2*)h1b;
#pragma unroll
        for (int q = 0; q < 8; ++q) {
            ulonglong2 v0 = hv[2 * q], v1 = hv[2 * q + 1];
            ffma2(q0, v0.x, w2p[4 * q + 0]); ffma2(q1, v0.y, w2p[4 * q + 1]);
            ffma2(q2, v1.x, w2p[4 * q + 2]); ffma2(q3, v1.y, w2p[4 * q + 3]);
        }
        h2b[t] = ftanh(hsum4(q0, q1, q2, q3));
    };
    auto gdot = [&]() -> float {     // g = M[:,t] . h2
        ull d0 = 0, d1 = 0, d2 = 0, d3 = 0;
        const ulonglong2* gv = (const ulonglong2*)h2b;
#pragma unroll
        for (int q = 0; q < 8; ++q) {
            ulonglong2 v0 = gv[2 * q], v1 = gv[2 * q + 1];
            ffma2(d0, v0.x, Mp[4 * q + 0]); ffma2(d1, v0.y, Mp[4 * q + 1]);
            ffma2(d2, v1.x, Mp[4 * q + 2]); ffma2(d3, v1.y, Mp[4 * q + 3]);
        }
        return hsum4(d0, d1, d2, d3);
    };
    auto pdot = [&](float* dst) {    // W3 half-K trajectory partial
        ull p0 = 0, p1 = 0;
        const ulonglong2* ph = (const ulonglong2*)(h2b + kh * 32);
#pragma unroll
        for (int q = 0; q < 8; ++q) {
            ulonglong2 wv = pw[q], hv = ph[q];
            ffma2(p0, hv.x, wv.x);
            ffma2(p1, hv.y, wv.y);
        }
        dst[t] = hsum(addf2(p0, p1));
    };

    float Hp = 0.0f;

#pragma unroll 1
    for (int j = 0; j < 33; ++j) {
        const int base = 3 * j;
        const float H  = tsb[base + 3] - tsb[base];
        const float s0 = sArr[(base + 0) * 64 + t];
        const float s1 = sArr[(base + 1) * 64 + t];
        const float s2 = sArr[(base + 2) * 64 + t];
        const float s3 = sArr[(base + 3) * 64 + t];
        const float be1 = bb1 + s0;
        // stage-2 bias: exact trapezoid mean of the treatment over the step
        const float beM = bb1 + (1.0f / 6.0f) * (s0 + 2.0f * (s1 + s2) + s3);

        // ================= eval 1 (k1 at t_base) =================
        h1b[t] = ftanh(A + be1);
        __syncthreads();                                   // BAR1: h1 ready
        layer2();
        // finalize previous step's 3 outputs (warp 0, in layer2's shadow)
        if (j > 0 && t < 32) {
            const float k1v = p3a[t] + p3a[t + 32] + bb3;
            const float k2v = p3b[t] + p3b[t + 32] + bb3;
            const float Hp9 = Hp * (1.0f / 9.0f);
            out[(base - 2) * 32 + t] = fmaf(Hp9, 2.0f * k1v + k2v, x);
            out[(base - 1) * 32 + t] = fmaf(2.0f * Hp9, k1v + 2.0f * k2v, x);
            x = fmaf(Hp, k2v, x);
            out[base * 32 + t] = x;
        }
        __syncthreads();                                   // BAR2: h2 ready
        {
            const float g1 = gdot();
            const float Amid = fmaf(0.5f * H, g1 + c3, A);
            h1b[t] = ftanh(Amid + beM);                    // critical chain
            pdot(p3a);                                     // fills BAR3 shadow
        }
        __syncthreads();                                   // BAR3: h1 ready

        // ================= eval 2 (k2, averaged treatment) =================
        layer2();
        __syncthreads();                                   // BAR4: h2 ready
        {
            const float g2 = gdot();
            A = fmaf(H, g2 + c3, A);                       // critical chain
            pdot(p3b);                                     // fills loop-head shadow
        }
        Hp = H;
    }

    // -------- outputs of last step (knots 97, 98, 99) --------
    __syncthreads();
    if (t < 32) {
        const float k1v = p3a[t] + p3a[t + 32] + bb3;
        const float k2v = p3b[t] + p3b[t + 32] + bb3;
        const float Hp9 = Hp * (1.0f / 9.0f);
        out[97 * 32 + t] = fmaf(Hp9, 2.0f * k1v + k2v, x);
        out[98 * 32 + t] = fmaf(2.0f * Hp9, k1v + 2.0f * k2v, x);
        out[99 * 32 + t] = fmaf(Hp, k2v, x);
    }
}

extern "C" void kernel_launch(void* const* d_in, const int* in_sizes, int n_in,
                              void* d_out, int out_size) {
    const float* x0    = (const float*)d_in[0];
    const float* treat = (const float*)d_in[1];
    const float* ts    = (const float*)d_in[2];
    const float* W1    = (const float*)d_in[3];
    const float* b1    = (const float*)d_in[4];
    const float* W2    = (const float*)d_in[5];
    const float* b2    = (const float*)d_in[6];
    const float* W3    = (const float*)d_in[7];
    const float* b3    = (const float*)d_in[8];
    float* out = (float*)d_out;

    ode_fused_kernel<<<1, 64>>>(x0, treat, ts, W1, b1, W2, b2, W3, b3, out);
}

// round 12
// speedup vs baseline: 4.8145x; 1.0714x over previous
#include <cuda_runtime.h>
#include <cuda_bf16.h>

// Counterfactual neural-ODE in layer-1 PRE-ACTIVATION space (M = W3@W1
// precomputed in-kernel, state A = W1^T x). R11: midpoint RK2 over QUAD
// ts-segments (24 steps x 4 + 1 step x 3 = 50 RHS evals). Stage-2 treatment
// bias is the exact trapezoid mean over the step (kills forcing aliasing
// across interior kinks). Interior-knot outputs use the order-2 quadratic
// dense output  x + H*(th*(1-th)*k1 + th^2*k2). pdot/finalize issue into
// barrier shadows; gdot->A->tanh is the critical chain.

typedef unsigned long long ull;

__device__ __forceinline__ ull pack2(float lo, float hi) {
    ull r; asm("mov.b64 %0, {%1, %2};" : "=l"(r) : "f"(lo), "f"(hi)); return r;
}
__device__ __forceinline__ ull addf2(ull a, ull b) {
    ull d; asm("add.rn.f32x2 %0, %1, %2;" : "=l"(d) : "l"(a), "l"(b)); return d;
}
__device__ __forceinline__ void ffma2(ull& d, ull a, ull b) {
    asm("fma.rn.f32x2 %0, %1, %2, %3;" : "=l"(d) : "l"(a), "l"(b), "l"(d));
}
__device__ __forceinline__ float hsum(ull v) {
    float lo, hi; asm("mov.b64 {%0, %1}, %2;" : "=f"(lo), "=f"(hi) : "l"(v));
    return lo + hi;
}
__device__ __forceinline__ float hsum4(ull a, ull b, ull c, ull d) {
    return hsum(addf2(addf2(a, b), addf2(c, d)));
}
__device__ __forceinline__ float ftanh(float x) {
    float r; asm("tanh.approx.f32 %0, %1;" : "=f"(r) : "f"(x)); return r;
}

__global__ void __launch_bounds__(64, 1)
ode_fused_kernel(const float* __restrict__ x0,
                 const float* __restrict__ treat,   // [100,4]
                 const float* __restrict__ ts,      // [100]
                 const float* __restrict__ W1,      // [36,64]
                 const float* __restrict__ b1,      // [64]
                 const float* __restrict__ W2,      // [64,64]
                 const float* __restrict__ b2,      // [64]
                 const float* __restrict__ W3,      // [64,32]
                 const float* __restrict__ b3,      // [32]
                 float* __restrict__ out)           // [100,32]
{
    __shared__ __align__(16) float h1b[64];
    __shared__ __align__(16) float h2b[64];
    __shared__ __align__(16) float p3a[64];       // eval-1 (k1) W3 partials
    __shared__ __align__(16) float p3b[64];       // eval-2 (k2) W3 partials
    __shared__ __align__(16) float w3s[2048];     // W3 staged (prologue)
    __shared__ __align__(16) float w3t[32 * 68];  // W3 transposed+padded
    __shared__ __align__(16) float trb[400];
    __shared__ __align__(16) float sArr[100 * 64]; // per-thread treatment dots
    __shared__ float tsb[104];

    const int t  = threadIdx.x;
    const int i3 = t & 31;
    const int kh = t >> 5;

    for (int j = t; j < 2048; j += 64) w3s[j] = W3[j];
    for (int j = t; j < 400;  j += 64) trb[j] = treat[j];
    for (int j = t; j < 100;  j += 64) tsb[j] = ts[j];
    if (t < 32) { h1b[t] = x0[t]; h2b[t] = b3[t]; out[t] = x0[t]; }
    __syncthreads();

    // ---- W1 column t ----
    ull w1p[16];
#pragma unroll
    for (int j = 0; j < 16; ++j)
        w1p[j] = pack2(W1[(2 * j) * 64 + t], W1[(2 * j + 1) * 64 + t]);
    const ull w1ta = pack2(W1[32 * 64 + t], W1[33 * 64 + t]);
    const ull w1tb = pack2(W1[34 * 64 + t], W1[35 * 64 + t]);
    const float bb1 = b1[t];
    const float bb2 = b2[t];
    const float bb3 = (t < 32) ? b3[t] : 0.0f;

    // ---- A0 = W1col . x0  and  c3 = W1col . b3 ----
    float A, c3;
    {
        ull a0 = 0, a1 = 0, a2 = 0, a3 = 0, e0 = 0, e1 = 0, e2 = 0, e3 = 0;
        const ulonglong2* sx = (const ulonglong2*)h1b;
        const ulonglong2* sb = (const ulonglong2*)h2b;
#pragma unroll
        for (int q = 0; q < 4; ++q) {
            ulonglong2 vx0 = sx[2 * q], vx1 = sx[2 * q + 1];
            ulonglong2 vb0 = sb[2 * q], vb1 = sb[2 * q + 1];
            ffma2(a0, vx0.x, w1p[4 * q + 0]); ffma2(a1, vx0.y, w1p[4 * q + 1]);
            ffma2(a2, vx1.x, w1p[4 * q + 2]); ffma2(a3, vx1.y, w1p[4 * q + 3]);
            ffma2(e0, vb0.x, w1p[4 * q + 0]); ffma2(e1, vb0.y, w1p[4 * q + 1]);
            ffma2(e2, vb1.x, w1p[4 * q + 2]); ffma2(e3, vb1.y, w1p[4 * q + 3]);
        }
        A  = hsum4(a0, a1, a2, a3);
        c3 = hsum4(e0, e1, e2, e3);
    }

    // ---- M column t: Mp[j] = (M[2j,t], M[2j+1,t]),  M[k,t] = W3[k,:].W1[:,t]
    ull Mp[32];
#pragma unroll
    for (int j = 0; j < 32; ++j) {
        ull m0 = 0, m1 = 0, n0 = 0, n1 = 0;
        const ulonglong2* r0 = (const ulonglong2*)(w3s + (2 * j) * 32);
        const ulonglong2* r1 = (const ulonglong2*)(w3s + (2 * j + 1) * 32);
#pragma unroll
        for (int q = 0; q < 4; ++q) {
            ulonglong2 u0 = r0[2 * q], u1 = r0[2 * q + 1];
            ulonglong2 v0 = r1[2 * q], v1 = r1[2 * q + 1];
            ffma2(m0, u0.x, w1p[4 * q + 0]); ffma2(m1, u0.y, w1p[4 * q + 1]);
            ffma2(m0, u1.x, w1p[4 * q + 2]); ffma2(m1, u1.y, w1p[4 * q + 3]);
            ffma2(n0, v0.x, w1p[4 * q + 0]); ffma2(n1, v0.y, w1p[4 * q + 1]);
            ffma2(n0, v1.x, w1p[4 * q + 2]); ffma2(n1, v1.y, w1p[4 * q + 3]);
        }
        Mp[j] = pack2(hsum(addf2(m0, m1)), hsum(addf2(n0, n1)));
    }

    // ---- W2 column t (registers) ----
    ull w2p[32];
#pragma unroll
    for (int j = 0; j < 32; ++j)
        w2p[j] = pack2(W2[(2 * j) * 64 + t], W2[(2 * j + 1) * 64 + t]);

    // ---- W3 transpose into SMEM (trajectory partials read it via LDS) ----
    for (int j = t; j < 2048; j += 64) {
        int k = j >> 5, i = j & 31;
        w3t[i * 68 + k] = w3s[j];
    }

    // ---- per-thread treatment dots: sArr[j][t] = W1_tr[:,t] . tr_j ----
#pragma unroll 4
    for (int j = 0; j < 100; ++j) {
        ull u = 0;
        const ulonglong2 v = *(const ulonglong2*)(trb + 4 * j);
        ffma2(u, v.x, w1ta); ffma2(u, v.y, w1tb);
        sArr[j * 64 + t] = hsum(u);
    }

    float x = (t < 32) ? x0[t] : 0.0f;
    __syncthreads();   // prologue SMEM writes published

    const ulonglong2* pw = (const ulonglong2*)(w3t + i3 * 68 + kh * 32);

    // -------- reusable phases --------
    auto layer2 = [&]() {
        ull q0 = pack2(bb2, 0.0f), q1 = 0, q2 = 0, q3 = 0;
        const ulonglong2* hv = (const ulonglong2*)h1b;
#pragma unroll
        for (int q = 0; q < 8; ++q) {
            ulonglong2 v0 = hv[2 * q], v1 = hv[2 * q + 1];
            ffma2(q0, v0.x, w2p[4 * q + 0]); ffma2(q1, v0.y, w2p[4 * q + 1]);
            ffma2(q2, v1.x, w2p[4 * q + 2]); ffma2(q3, v1.y, w2p[4 * q + 3]);
        }
        h2b[t] = ftanh(hsum4(q0, q1, q2, q3));
    };
    auto gdot = [&]() -> float {     // g = M[:,t] . h2
        ull d0 = 0, d1 = 0, d2 = 0, d3 = 0;
        const ulonglong2* gv = (const ulonglong2*)h2b;
#pragma unroll
        for (int q = 0; q < 8; ++q) {
            ulonglong2 v0 = gv[2 * q], v1 = gv[2 * q + 1];
            ffma2(d0, v0.x, Mp[4 * q + 0]); ffma2(d1, v0.y, Mp[4 * q + 1]);
            ffma2(d2, v1.x, Mp[4 * q + 2]); ffma2(d3, v1.y, Mp[4 * q + 3]);
        }
        return hsum4(d0, d1, d2, d3);
    };
    auto pdot = [&](float* dst) {    // W3 half-K trajectory partial
        ull p0 = 0, p1 = 0;
        const ulonglong2* ph = (const ulonglong2*)(h2b + kh * 32);
#pragma unroll
        for (int q = 0; q < 8; ++q) {
            ulonglong2 wv = pw[q], hv = ph[q];
            ffma2(p0, hv.x, wv.x);
            ffma2(p1, hv.y, wv.y);
        }
        dst[t] = hsum(addf2(p0, p1));
    };

    float Hp = 0.0f;

    // 25 steps: j=0..23 cover 4 segments each, j=24 covers the last 3.
#pragma unroll 1
    for (int j = 0; j < 25; ++j) {
        const int base = 4 * j;
        const int m = (j < 24) ? 4 : 3;
        const float H = tsb[base + m] - tsb[base];
        const float s0 = sArr[(base + 0) * 64 + t];
        const float s1 = sArr[(base + 1) * 64 + t];
        const float s2 = sArr[(base + 2) * 64 + t];
        const float s3 = sArr[(base + 3) * 64 + t];
        const float be1 = bb1 + s0;
        // stage-2 bias: exact trapezoid mean of the treatment over the step
        float beM;
        if (m == 4) {
            const float s4 = sArr[(base + 4) * 64 + t];
            beM = bb1 + 0.125f * (s0 + s4) + 0.25f * (s1 + s2 + s3);
        } else {
            beM = bb1 + (1.0f / 6.0f) * (s0 + 2.0f * (s1 + s2) + s3);
        }

        // ================= eval 1 (k1 at t_base) =================
        h1b[t] = ftanh(A + be1);
        __syncthreads();                                   // BAR1: h1 ready
        layer2();
        // finalize previous step's outputs (always m=4; warp 0, layer2 shadow)
        if (j > 0 && t < 32) {
            const float k1v = p3a[t] + p3a[t + 32] + bb3;
            const float k2v = p3b[t] + p3b[t + 32] + bb3;
            // th = 1/4, 1/2, 3/4:  x + H*(th*(1-th)*k1 + th^2*k2)
            out[(base - 3) * 32 + t] =
                fmaf(Hp * 0.0625f, 3.0f * k1v + k2v, x);
            out[(base - 2) * 32 + t] =
                fmaf(Hp * 0.25f, k1v + k2v, x);
            out[(base - 1) * 32 + t] =
                fmaf(Hp * 0.1875f, k1v + 3.0f * k2v, x);
            x = fmaf(Hp, k2v, x);
            out[base * 32 + t] = x;
        }
        __syncthreads();                                   // BAR2: h2 ready
        {
            const float g1 = gdot();
            const float Amid = fmaf(0.5f * H, g1 + c3, A);
            h1b[t] = ftanh(Amid + beM);                    // critical chain
            pdot(p3a);                                     // fills BAR3 shadow
        }
        __syncthreads();                                   // BAR3: h1 ready

        // ================= eval 2 (k2, averaged treatment) =================
        layer2();
        __syncthreads();                                   // BAR4: h2 ready
        {
            const float g2 = gdot();
            A = fmaf(H, g2 + c3, A);                       // critical chain
            pdot(p3b);                                     // fills loop-head shadow
        }
        Hp = H;
    }

    // -------- outputs of last step (m=3: knots 97, 98, 99) --------
    __syncthreads();
    if (t < 32) {
        const float k1v = p3a[t] + p3a[t + 32] + bb3;
        const float k2v = p3b[t] + p3b[t + 32] + bb3;
        const float Hp9 = Hp * (1.0f / 9.0f);
        out[97 * 32 + t] = fmaf(Hp9, 2.0f * k1v + k2v, x);
        out[98 * 32 + t] = fmaf(2.0f * Hp9, k1v + 2.0f * k2v, x);
        out[99 * 32 + t] = fmaf(Hp, k2v, x);
    }
}

extern "C" void kernel_launch(void* const* d_in, const int* in_sizes, int n_in,
                              void* d_out, int out_size) {
    const float* x0    = (const float*)d_in[0];
    const float* treat = (const float*)d_in[1];
    const float* ts    = (const float*)d_in[2];
    const float* W1    = (const float*)d_in[3];
    const float* b1    = (const float*)d_in[4];
    const float* W2    = (const float*)d_in[5];
    const float* b2    = (const float*)d_in[6];
    const float* W3    = (const float*)d_in[7];
    const float* b3    = (const float*)d_in[8];
    float* out = (float*)d_out;

    ode_fused_kernel<<<1, 64>>>(x0, treat, ts, W1, b1, W2, b2, W3, b3, out);
}

// round 13
// speedup vs baseline: 6.5856x; 1.3679x over previous
#include <cuda_runtime.h>
#include <cuda_bf16.h>

// Counterfactual neural-ODE in layer-1 PRE-ACTIVATION space (M = W3@W1,
// A = W1^T x). R13: (a) midpoint RK2 over 6-segment steps (16x6 + 1x3 = 34
// RHS evals), stage-2 bias = exact trapezoid mean of the treatment over the
// step; order-2 dense output at interior knots. (b) 128 threads, warp-
// specialized: warps 0-1 run ONLY the serial recursion (tanh->L2->Mdot);
// warps 2-3 (separate SMSPs) do W3 trajectory partials, dense outputs, all
// STGs, and precompute the per-step (be1,beM,H) table so the critical loop
// head is a single LDS.128.

typedef unsigned long long ull;

__device__ __forceinline__ ull pack2(float lo, float hi) {
    ull r; asm("mov.b64 %0, {%1, %2};" : "=l"(r) : "f"(lo), "f"(hi)); return r;
}
__device__ __forceinline__ ull addf2(ull a, ull b) {
    ull d; asm("add.rn.f32x2 %0, %1, %2;" : "=l"(d) : "l"(a), "l"(b)); return d;
}
__device__ __forceinline__ void ffma2(ull& d, ull a, ull b) {
    asm("fma.rn.f32x2 %0, %1, %2, %3;" : "=l"(d) : "l"(a), "l"(b), "l"(d));
}
__device__ __forceinline__ float hsum(ull v) {
    float lo, hi; asm("mov.b64 {%0, %1}, %2;" : "=f"(lo), "=f"(hi) : "l"(v));
    return lo + hi;
}
__device__ __forceinline__ float hsum4(ull a, ull b, ull c, ull d) {
    return hsum(addf2(addf2(a, b), addf2(c, d)));
}
__device__ __forceinline__ float ftanh(float x) {
    float r; asm("tanh.approx.f32 %0, %1;" : "=f"(r) : "f"(x)); return r;
}

__global__ void __launch_bounds__(128, 1)
ode_fused_kernel(const float* __restrict__ x0,
                 const float* __restrict__ treat,   // [100,4]
                 const float* __restrict__ ts,      // [100]
                 const float* __restrict__ W1,      // [36,64]
                 const float* __restrict__ b1,      // [64]
                 const float* __restrict__ W2,      // [64,64]
                 const float* __restrict__ b2,      // [64]
                 const float* __restrict__ W3,      // [64,32]
                 const float* __restrict__ b3,      // [32]
                 float* __restrict__ out)           // [100,32]
{
    __shared__ __align__(16) float h1b[64];
    __shared__ __align__(16) float h2b[64];
    __shared__ __align__(16) float p3a[64];       // eval-1 (k1) W3 partials
    __shared__ __align__(16) float p3b[64];       // eval-2 (k2) W3 partials
    __shared__ __align__(16) float w3s[2048];     // W3 staged (prologue)
    __shared__ __align__(16) float w3t[32 * 68];  // W3 transposed+padded
    __shared__ __align__(16) float trb[400];
    __shared__ __align__(16) float4 beP[17 * 64]; // (be1, beM, H, 0) per step
    __shared__ float tsb[104];

    const int t   = threadIdx.x;
    const int tc  = t & 63;          // logical column
    const int grp = t >> 6;          // 0 = compute warps, 1 = helper warps
    const int i3  = tc & 31;
    const int kh  = tc >> 5;

    for (int j = t; j < 2048; j += 128) w3s[j] = W3[j];
    for (int j = t; j < 400;  j += 128) trb[j] = treat[j];
    for (int j = t; j < 100;  j += 128) tsb[j] = ts[j];
    if (t < 32) { h1b[t] = x0[t]; h2b[t] = b3[t]; out[t] = x0[t]; }
    __syncthreads();

    const float bb2 = b2[tc];
    const float bb3 = (tc < 32) ? b3[tc] : 0.0f;

    float A = 0.0f, c3 = 0.0f;
    ull Mp[32];
    ull w2p[32];

    if (grp == 0) {
        // ---- compute-group prologue: W1 col, A0, c3, M = W3@W1 col, W2 col
        ull w1p[16];
#pragma unroll
        for (int j = 0; j < 16; ++j)
            w1p[j] = pack2(W1[(2 * j) * 64 + tc], W1[(2 * j + 1) * 64 + tc]);
        {
            ull a0 = 0, a1 = 0, a2 = 0, a3 = 0, e0 = 0, e1 = 0, e2 = 0, e3 = 0;
            const ulonglong2* sx = (const ulonglong2*)h1b;
            const ulonglong2* sb = (const ulonglong2*)h2b;
#pragma unroll
            for (int q = 0; q < 4; ++q) {
                ulonglong2 vx0 = sx[2 * q], vx1 = sx[2 * q + 1];
                ulonglong2 vb0 = sb[2 * q], vb1 = sb[2 * q + 1];
                ffma2(a0, vx0.x, w1p[4 * q + 0]); ffma2(a1, vx0.y, w1p[4 * q + 1]);
                ffma2(a2, vx1.x, w1p[4 * q + 2]); ffma2(a3, vx1.y, w1p[4 * q + 3]);
                ffma2(e0, vb0.x, w1p[4 * q + 0]); ffma2(e1, vb0.y, w1p[4 * q + 1]);
                ffma2(e2, vb1.x, w1p[4 * q + 2]); ffma2(e3, vb1.y, w1p[4 * q + 3]);
            }
            A  = hsum4(a0, a1, a2, a3);
            c3 = hsum4(e0, e1, e2, e3);
        }
#pragma unroll
        for (int j = 0; j < 32; ++j) {
            ull m0 = 0, m1 = 0, n0 = 0, n1 = 0;
            const ulonglong2* r0 = (const ulonglong2*)(w3s + (2 * j) * 32);
            const ulonglong2* r1 = (const ulonglong2*)(w3s + (2 * j + 1) * 32);
#pragma unroll
            for (int q = 0; q < 4; ++q) {
                ulonglong2 u0 = r0[2 * q], u1 = r0[2 * q + 1];
                ulonglong2 v0 = r1[2 * q], v1 = r1[2 * q + 1];
                ffma2(m0, u0.x, w1p[4 * q + 0]); ffma2(m1, u0.y, w1p[4 * q + 1]);
                ffma2(m0, u1.x, w1p[4 * q + 2]); ffma2(m1, u1.y, w1p[4 * q + 3]);
                ffma2(n0, v0.x, w1p[4 * q + 0]); ffma2(n1, v0.y, w1p[4 * q + 1]);
                ffma2(n0, v1.x, w1p[4 * q + 2]); ffma2(n1, v1.y, w1p[4 * q + 3]);
            }
            Mp[j] = pack2(hsum(addf2(m0, m1)), hsum(addf2(n0, n1)));
        }
#pragma unroll
        for (int j = 0; j < 32; ++j)
            w2p[j] = pack2(W2[(2 * j) * 64 + tc], W2[(2 * j + 1) * 64 + tc]);
    } else {
        // ---- helper-group prologue: W3 transpose + per-step bias/H table
        const float bb1h = b1[tc];
        const ull w1ta = pack2(W1[32 * 64 + tc], W1[33 * 64 + tc]);
        const ull w1tb = pack2(W1[34 * 64 + tc], W1[35 * 64 + tc]);
        for (int j = tc; j < 2048; j += 64) {
            int k = j >> 5, i = j & 31;
            w3t[i * 68 + k] = w3s[j];
        }
#pragma unroll 1
        for (int jj = 0; jj < 17; ++jj) {
            const int base = 6 * jj;
            const int m = (jj < 16) ? 6 : 3;
            float s[7];
            for (int i = 0; i <= m; ++i) {
                ull u = 0;
                const ulonglong2 v = *(const ulonglong2*)(trb + 4 * (base + i));
                ffma2(u, v.x, w1ta); ffma2(u, v.y, w1tb);
                s[i] = hsum(u);
            }
            float acc = s[0] + s[m];
            for (int i = 1; i < m; ++i) acc += 2.0f * s[i];
            const float inv2m = (m == 6) ? (1.0f / 12.0f) : (1.0f / 6.0f);
            float4 e;
            e.x = bb1h + s[0];                 // be1 (k1 stage)
            e.y = bb1h + acc * inv2m;          // beM (averaged stage)
            e.z = tsb[base + m] - tsb[base];   // H
            e.w = 0.0f;
            beP[jj * 64 + tc] = e;
        }
    }

    float x = (grp == 1 && tc < 32) ? x0[tc] : 0.0f;
    __syncthreads();   // prologue tables published

    const ulonglong2* pw = (const ulonglong2*)(w3t + i3 * 68 + kh * 32);

    auto layer2 = [&]() {
        ull q0 = pack2(bb2, 0.0f), q1 = 0, q2 = 0, q3 = 0;
        const ulonglong2* hv = (const ulonglong2*)h1b;
#pragma unroll
        for (int q = 0; q < 8; ++q) {
            ulonglong2 v0 = hv[2 * q], v1 = hv[2 * q + 1];
            ffma2(q0, v0.x, w2p[4 * q + 0]); ffma2(q1, v0.y, w2p[4 * q + 1]);
            ffma2(q2, v1.x, w2p[4 * q + 2]); ffma2(q3, v1.y, w2p[4 * q + 3]);
        }
        h2b[tc] = ftanh(hsum4(q0, q1, q2, q3));
    };
    auto gdot = [&]() -> float {     // g = M[:,tc] . h2
        ull d0 = 0, d1 = 0, d2 = 0, d3 = 0;
        const ulonglong2* gv = (const ulonglong2*)h2b;
#pragma unroll
        for (int q = 0; q < 8; ++q) {
            ulonglong2 v0 = gv[2 * q], v1 = gv[2 * q + 1];
            ffma2(d0, v0.x, Mp[4 * q + 0]); ffma2(d1, v0.y, Mp[4 * q + 1]);
            ffma2(d2, v1.x, Mp[4 * q + 2]); ffma2(d3, v1.y, Mp[4 * q + 3]);
        }
        return hsum4(d0, d1, d2, d3);
    };
    auto pdot = [&](float* dst) {    // W3 half-K trajectory partial (helpers)
        ull p0 = 0, p1 = 0;
        const ulonglong2* ph = (const ulonglong2*)(h2b + kh * 32);
#pragma unroll
        for (int q = 0; q < 8; ++q) {
            ulonglong2 wv = pw[q], hv = ph[q];
            ffma2(p0, hv.x, wv.x);
            ffma2(p1, hv.y, wv.y);
        }
        dst[tc] = hsum(addf2(p0, p1));
    };

    float4 be = beP[tc];             // step 0 (prefetched thereafter)
    float Hp = 0.0f;

#pragma unroll 1
    for (int j = 0; j < 17; ++j) {
        const float H = be.z;

        // ================= eval 1 (k1 at t_base) =================
        if (grp == 0) h1b[tc] = ftanh(A + be.x);
        __syncthreads();                                   // BAR1: h1 ready
        if (grp == 0) {
            layer2();
        } else if (j > 0 && tc < 32) {
            // dense outputs of previous step (m=6), th = i/6
            const float k1v = p3a[tc] + p3a[tc + 32] + bb3;
            const float k2v = p3b[tc] + p3b[tc + 32] + bb3;
            const float c = Hp * (1.0f / 36.0f);
            float* o = out + (6 * j - 6) * 32 + tc;
            o[1 * 32] = fmaf(c, 5.0f * k1v +        k2v, x);
            o[2 * 32] = fmaf(c, 8.0f * k1v + 4.0f * k2v, x);
            o[3 * 32] = fmaf(c, 9.0f * (k1v + k2v),      x);
            o[4 * 32] = fmaf(c, 8.0f * k1v + 16.0f * k2v, x);
            o[5 * 32] = fmaf(c, 5.0f * k1v + 25.0f * k2v, x);
            x = fmaf(Hp, k2v, x);
            o[6 * 32] = x;
        }
        __syncthreads();                                   // BAR2: h2 ready
        if (grp == 0) {
            const float g1 = gdot();
            const float Amid = fmaf(0.5f * H, g1 + c3, A);
            h1b[tc] = ftanh(Amid + be.y);                  // critical chain
        } else {
            pdot(p3a);                                     // k1 partial
        }
        __syncthreads();                                   // BAR3: h1 ready

        // ================= eval 2 (k2, averaged treatment) =================
        if (grp == 0) layer2();
        __syncthreads();                                   // BAR4: h2 ready
        if (grp == 0) {
            const float g2 = gdot();
            A = fmaf(H, g2 + c3, A);                       // critical chain
        } else {
            pdot(p3b);                                     // k2 partial
        }
        Hp = H;
        be = beP[((j < 16) ? (j + 1) : 16) * 64 + tc];     // prefetch next
    }

    // -------- outputs of last step (m=3: knots 97, 98, 99) --------
    __syncthreads();
    if (grp == 1 && tc < 32) {
        const float k1v = p3a[tc] + p3a[tc + 32] + bb3;
        const float k2v = p3b[tc] + p3b[tc + 32] + bb3;
        const float Hp9 = Hp * (1.0f / 9.0f);
        out[97 * 32 + tc] = fmaf(Hp9, 2.0f * k1v + k2v, x);
        out[98 * 32 + tc] = fmaf(2.0f * Hp9, k1v + 2.0f * k2v, x);
        out[99 * 32 + tc] = fmaf(Hp, k2v, x);
    }
}

extern "C" void kernel_launch(void* const* d_in, const int* in_sizes, int n_in,
                              void* d_out, int out_size) {
    const float* x0    = (const float*)d_in[0];
    const float* treat = (const float*)d_in[1];
    const float* ts    = (const float*)d_in[2];
    const float* W1    = (const float*)d_in[3];
    const float* b1    = (const float*)d_in[4];
    const float* W2    = (const float*)d_in[5];
    const float* b2    = (const float*)d_in[6];
    const float* W3    = (const float*)d_in[7];
    const float* b3    = (const float*)d_in[8];
    float* out = (float*)d_out;

    ode_fused_kernel<<<1, 128>>>(x0, treat, ts, W1, b1, W2, b2, W3, b3, out);
}